// round 2
// baseline (speedup 1.0000x reference)
#include <cuda_runtime.h>

typedef unsigned long long ULL;

// ---------- packed f32x2 helpers (Blackwell sm_103a) ----------
__device__ __forceinline__ ULL f2x2_fma(ULL a, ULL b, ULL c) {
    ULL d;
    asm("fma.rn.f32x2 %0, %1, %2, %3;" : "=l"(d) : "l"(a), "l"(b), "l"(c));
    return d;
}
__device__ __forceinline__ void f2x2_unpack(ULL v, float& lo, float& hi) {
    asm("mov.b64 {%0, %1}, %2;" : "=f"(lo), "=f"(hi) : "l"(v));
}

// ---------- problem constants (fixed instance) ----------
constexpr int S = 3, G = 8, B = 2048, C = 512, P = 64;
constexpr int N = S * G * B;              // 49152
constexpr int OUT_ELEMS = G * P * C;      // 262144
constexpr int KTOT = S * B;               // 6144 rows per graph
constexpr int KS = 9;                     // split-K for GEMM2
constexpr int KCHUNK = 688;               // 9*688 >= 6144, multiple of 16

// ---------- device scratch (no allocations allowed) ----------
__device__ float g_csq[P];
__device__ float g_ivb[P];
__device__ float g_partial[(size_t)KS * OUT_ELEMS];

// ---------- prep: |c|^2 and 1/beta ----------
__global__ void prep_kernel(const float* __restrict__ W, const float* __restrict__ sf) {
    int p = threadIdx.x;
    if (p >= P) return;
    const float4* wr = reinterpret_cast<const float4*>(W + (size_t)p * C);
    float s = 0.f;
#pragma unroll 8
    for (int i = 0; i < C / 4; i++) {
        float4 v = wr[i];
        s += v.x * v.x + v.y * v.y + v.z * v.z + v.w * v.w;
    }
    g_csq[p] = s;
    g_ivb[p] = 1.0f + __expf(-sf[p]);   // 1/sigmoid(sf)
}

// ---------- fused GEMM1 + softmax -> assign [N, P] ----------
constexpr int BM = 128;       // rows per block
constexpr int KC = 16;        // k per stage
constexpr int NSTG = C / KC;  // 32

__global__ __launch_bounds__(128, 2) void assign_kernel(
    const float* __restrict__ X, const float* __restrict__ W,
    float* __restrict__ assign_out)
{
    __shared__ __align__(16) float As[2][KC][BM];       // 16 KB
    __shared__ __align__(16) float Wd[2][KC][2 * P];    // 16 KB, duplicated W
    __shared__ float Xsq[BM];
    __shared__ float Csq[P];
    __shared__ float Ivb[P];

    const int t = threadIdx.x;
    const int row_base = blockIdx.x * BM;
    const int r0 = (t >> 3) * 8;   // 8 rows (4 f32x2 row-pairs)
    const int c0 = (t & 7) * 8;    // 8 cols
    const int wp = t & 63;         // p index owned for W loads
    const int wh = t >> 6;         // which 8 of the 16 k's

    if (t < P) { Csq[t] = g_csq[t]; Ivb[t] = g_ivb[t]; }

    const float* xrow = X + (size_t)(row_base + t) * C;   // thread t owns row t
    const float* wrow = W + (size_t)wp * C + wh * 8;

    ULL acc[4][8];
#pragma unroll
    for (int i = 0; i < 4; i++)
#pragma unroll
        for (int j = 0; j < 8; j++) acc[i][j] = 0ull;

    float xsq = 0.f;
    float4 al[4], wl[2];

    // prologue: stage 0 global loads + smem store
#pragma unroll
    for (int i = 0; i < 4; i++) al[i] = *reinterpret_cast<const float4*>(xrow + i * 4);
    wl[0] = *reinterpret_cast<const float4*>(wrow);
    wl[1] = *reinterpret_cast<const float4*>(wrow + 4);
#pragma unroll
    for (int i = 0; i < 4; i++) {
        As[0][i * 4 + 0][t] = al[i].x; As[0][i * 4 + 1][t] = al[i].y;
        As[0][i * 4 + 2][t] = al[i].z; As[0][i * 4 + 3][t] = al[i].w;
        xsq += al[i].x * al[i].x + al[i].y * al[i].y + al[i].z * al[i].z + al[i].w * al[i].w;
    }
#pragma unroll
    for (int h = 0; h < 2; h++) {
        const float v0 = (h == 0) ? wl[0].x : wl[1].x;
        const float v1 = (h == 0) ? wl[0].y : wl[1].y;
        const float v2 = (h == 0) ? wl[0].z : wl[1].z;
        const float v3 = (h == 0) ? wl[0].w : wl[1].w;
        *reinterpret_cast<float2*>(&Wd[0][wh * 8 + h * 4 + 0][2 * wp]) = make_float2(v0, v0);
        *reinterpret_cast<float2*>(&Wd[0][wh * 8 + h * 4 + 1][2 * wp]) = make_float2(v1, v1);
        *reinterpret_cast<float2*>(&Wd[0][wh * 8 + h * 4 + 2][2 * wp]) = make_float2(v2, v2);
        *reinterpret_cast<float2*>(&Wd[0][wh * 8 + h * 4 + 3][2 * wp]) = make_float2(v3, v3);
    }
    __syncthreads();

#pragma unroll 1
    for (int s = 0; s < NSTG; s++) {
        const int buf = s & 1;
        if (s + 1 < NSTG) {
            const int k0 = (s + 1) * KC;
#pragma unroll
            for (int i = 0; i < 4; i++)
                al[i] = *reinterpret_cast<const float4*>(xrow + k0 + i * 4);
            wl[0] = *reinterpret_cast<const float4*>(wrow + k0);
            wl[1] = *reinterpret_cast<const float4*>(wrow + k0 + 4);
        }
#pragma unroll
        for (int kk = 0; kk < KC; kk++) {
            ulonglong2 a01 = *reinterpret_cast<const ulonglong2*>(&As[buf][kk][r0]);
            ulonglong2 a23 = *reinterpret_cast<const ulonglong2*>(&As[buf][kk][r0 + 4]);
            ulonglong2 b01 = *reinterpret_cast<const ulonglong2*>(&Wd[buf][kk][2 * c0]);
            ulonglong2 b23 = *reinterpret_cast<const ulonglong2*>(&Wd[buf][kk][2 * c0 + 4]);
            ulonglong2 b45 = *reinterpret_cast<const ulonglong2*>(&Wd[buf][kk][2 * c0 + 8]);
            ulonglong2 b67 = *reinterpret_cast<const ulonglong2*>(&Wd[buf][kk][2 * c0 + 12]);
            ULL bd[8] = {b01.x, b01.y, b23.x, b23.y, b45.x, b45.y, b67.x, b67.y};
            ULL av[4] = {a01.x, a01.y, a23.x, a23.y};
#pragma unroll
            for (int i = 0; i < 4; i++)
#pragma unroll
                for (int j = 0; j < 8; j++)
                    acc[i][j] = f2x2_fma(av[i], bd[j], acc[i][j]);
        }
        if (s + 1 < NSTG) {
            const int nb = buf ^ 1;
#pragma unroll
            for (int i = 0; i < 4; i++) {
                As[nb][i * 4 + 0][t] = al[i].x; As[nb][i * 4 + 1][t] = al[i].y;
                As[nb][i * 4 + 2][t] = al[i].z; As[nb][i * 4 + 3][t] = al[i].w;
                xsq += al[i].x * al[i].x + al[i].y * al[i].y + al[i].z * al[i].z + al[i].w * al[i].w;
            }
#pragma unroll
            for (int h = 0; h < 2; h++) {
                const float v0 = (h == 0) ? wl[0].x : wl[1].x;
                const float v1 = (h == 0) ? wl[0].y : wl[1].y;
                const float v2 = (h == 0) ? wl[0].z : wl[1].z;
                const float v3 = (h == 0) ? wl[0].w : wl[1].w;
                *reinterpret_cast<float2*>(&Wd[nb][wh * 8 + h * 4 + 0][2 * wp]) = make_float2(v0, v0);
                *reinterpret_cast<float2*>(&Wd[nb][wh * 8 + h * 4 + 1][2 * wp]) = make_float2(v1, v1);
                *reinterpret_cast<float2*>(&Wd[nb][wh * 8 + h * 4 + 2][2 * wp]) = make_float2(v2, v2);
                *reinterpret_cast<float2*>(&Wd[nb][wh * 8 + h * 4 + 3][2 * wp]) = make_float2(v3, v3);
            }
        }
        __syncthreads();
    }

    Xsq[t] = xsq;
    __syncthreads();

    // ---- epilogue: softmax from registers via 8-lane shuffles ----
    // thread owns rows r0..r0+7 (acc pair i -> rows r0+2i, r0+2i+1), cols c0..c0+7
    float csq_j[8], ivb_j[8], xs_r[8];
#pragma unroll
    for (int j = 0; j < 8; j++) { csq_j[j] = Csq[c0 + j]; ivb_j[j] = Ivb[c0 + j]; }
#pragma unroll
    for (int i = 0; i < 8; i++) xs_r[i] = Xsq[r0 + i];

    float e[8][8];
#pragma unroll
    for (int i = 0; i < 4; i++) {
#pragma unroll
        for (int j = 0; j < 8; j++) {
            float lo, hi;
            f2x2_unpack(acc[i][j], lo, hi);
            e[2 * i][j]     = fminf(2.f * lo - xs_r[2 * i]     - csq_j[j], 0.f) * ivb_j[j];
            e[2 * i + 1][j] = fminf(2.f * hi - xs_r[2 * i + 1] - csq_j[j], 0.f) * ivb_j[j];
        }
    }

#pragma unroll
    for (int r = 0; r < 8; r++) {
        float m = e[r][0];
#pragma unroll
        for (int j = 1; j < 8; j++) m = fmaxf(m, e[r][j]);
        m = fmaxf(m, __shfl_xor_sync(0xffffffffu, m, 1));
        m = fmaxf(m, __shfl_xor_sync(0xffffffffu, m, 2));
        m = fmaxf(m, __shfl_xor_sync(0xffffffffu, m, 4));
        float sum = 0.f;
#pragma unroll
        for (int j = 0; j < 8; j++) { float ex = __expf(e[r][j] - m); e[r][j] = ex; sum += ex; }
        sum += __shfl_xor_sync(0xffffffffu, sum, 1);
        sum += __shfl_xor_sync(0xffffffffu, sum, 2);
        sum += __shfl_xor_sync(0xffffffffu, sum, 4);
        const float inv = 1.f / sum;
        float* orow = assign_out + (size_t)(row_base + r0 + r) * P + c0;
        *reinterpret_cast<float4*>(orow)     = make_float4(e[r][0] * inv, e[r][1] * inv, e[r][2] * inv, e[r][3] * inv);
        *reinterpret_cast<float4*>(orow + 4) = make_float4(e[r][4] * inv, e[r][5] * inv, e[r][6] * inv, e[r][7] * inv);
    }
}

// ---------- GEMM2: out[g] = assign_g^T @ feats_g  (split-K partials) ----------
constexpr int BC2 = 128;
constexpr int KC2 = 16;
constexpr int NST2 = KCHUNK / KC2;   // 43

__global__ __launch_bounds__(128, 2) void gemm2_kernel(
    const float* __restrict__ X, const float* __restrict__ Asn)
{
    __shared__ __align__(16) float Ad[2][KC2][2 * P];    // 16 KB, duplicated assign
    __shared__ __align__(16) float Fsm[2][KC2][BC2];     // 16 KB

    const int t = threadIdx.x;
    const int ct = blockIdx.x;   // c tile 0..3
    const int g  = blockIdx.y;   // graph 0..7
    const int ks = blockIdx.z;   // k split 0..KS-1

    const int p0 = (t >> 4) * 8;   // 8 p rows
    const int c0 = (t & 15) * 8;   // 8 cols = 4 f32x2 col-pairs

    const int jj = t >> 3;         // k-row within stage (0..15)
    const int part = t & 7;        // chunk within row

    const int j0 = ks * KCHUNK;
    const int cbase = ct * BC2;

    ULL acc[8][4];
#pragma unroll
    for (int i = 0; i < 8; i++)
#pragma unroll
        for (int j = 0; j < 4; j++) acc[i][j] = 0ull;

    float4 aa[2], ff[4];

    auto load_stage = [&](int stg) {
        const int j = j0 + stg * KC2 + jj;
        if (j < KTOT) {
            const int sidx = j >> 11;            // / B (2048)
            const int n = j & (B - 1);
            const size_t row = (size_t)sidx * (G * B) + (size_t)g * B + n;
            const float* ap = Asn + row * P + part * 8;
            const float* fp = X + row * C + cbase + part * 16;
            aa[0] = *reinterpret_cast<const float4*>(ap);
            aa[1] = *reinterpret_cast<const float4*>(ap + 4);
#pragma unroll
            for (int i = 0; i < 4; i++)
                ff[i] = *reinterpret_cast<const float4*>(fp + 4 * i);
        } else {
            aa[0] = aa[1] = make_float4(0.f, 0.f, 0.f, 0.f);
#pragma unroll
            for (int i = 0; i < 4; i++) ff[i] = make_float4(0.f, 0.f, 0.f, 0.f);
        }
    };
    auto store_stage = [&](int nb) {
        // duplicated assign: Ad[jj][2p] = Ad[jj][2p+1] = a_p
        *reinterpret_cast<float4*>(&Ad[nb][jj][2 * (part * 8)]) =
            make_float4(aa[0].x, aa[0].x, aa[0].y, aa[0].y);
        *reinterpret_cast<float4*>(&Ad[nb][jj][2 * (part * 8) + 4]) =
            make_float4(aa[0].z, aa[0].z, aa[0].w, aa[0].w);
        *reinterpret_cast<float4*>(&Ad[nb][jj][2 * (part * 8) + 8]) =
            make_float4(aa[1].x, aa[1].x, aa[1].y, aa[1].y);
        *reinterpret_cast<float4*>(&Ad[nb][jj][2 * (part * 8) + 12]) =
            make_float4(aa[1].z, aa[1].z, aa[1].w, aa[1].w);
#pragma unroll
        for (int i = 0; i < 4; i++)
            *reinterpret_cast<float4*>(&Fsm[nb][jj][part * 16 + 4 * i]) = ff[i];
    };

    load_stage(0);
    store_stage(0);
    __syncthreads();

#pragma unroll 1
    for (int s = 0; s < NST2; s++) {
        const int buf = s & 1;
        if (s + 1 < NST2) load_stage(s + 1);
#pragma unroll
        for (int kk = 0; kk < KC2; kk++) {
            ulonglong2 a01 = *reinterpret_cast<const ulonglong2*>(&Ad[buf][kk][2 * p0]);
            ulonglong2 a23 = *reinterpret_cast<const ulonglong2*>(&Ad[buf][kk][2 * p0 + 4]);
            ulonglong2 a45 = *reinterpret_cast<const ulonglong2*>(&Ad[buf][kk][2 * p0 + 8]);
            ulonglong2 a67 = *reinterpret_cast<const ulonglong2*>(&Ad[buf][kk][2 * p0 + 12]);
            ulonglong2 b01 = *reinterpret_cast<const ulonglong2*>(&Fsm[buf][kk][c0]);
            ulonglong2 b23 = *reinterpret_cast<const ulonglong2*>(&Fsm[buf][kk][c0 + 4]);
            ULL ad[8] = {a01.x, a01.y, a23.x, a23.y, a45.x, a45.y, a67.x, a67.y};
            ULL bv[4] = {b01.x, b01.y, b23.x, b23.y};
#pragma unroll
            for (int i = 0; i < 8; i++)
#pragma unroll
                for (int j = 0; j < 4; j++)
                    acc[i][j] = f2x2_fma(ad[i], bv[j], acc[i][j]);
        }
        if (s + 1 < NST2) store_stage(buf ^ 1);
        __syncthreads();
    }

    float* dst = g_partial + ((size_t)ks * G + g) * (size_t)(P * C);
#pragma unroll
    for (int i = 0; i < 8; i++) {
        const int p = p0 + i;
        float* drow = dst + (size_t)p * C + cbase + c0;
        ulonglong2 v0; v0.x = acc[i][0]; v0.y = acc[i][1];
        ulonglong2 v1; v1.x = acc[i][2]; v1.y = acc[i][3];
        *reinterpret_cast<ulonglong2*>(drow)     = v0;
        *reinterpret_cast<ulonglong2*>(drow + 4) = v1;
    }
}

// ---------- deterministic split-K reduction (vectorized) ----------
__global__ void reduce_kernel(float* __restrict__ out) {
    const int i = blockIdx.x * blockDim.x + threadIdx.x;
    if (i < OUT_ELEMS / 4) {
        const float4* src = reinterpret_cast<const float4*>(g_partial);
        float4 s = src[i];
#pragma unroll
        for (int ks = 1; ks < KS; ks++) {
            float4 v = src[(size_t)ks * (OUT_ELEMS / 4) + i];
            s.x += v.x; s.y += v.y; s.z += v.z; s.w += v.w;
        }
        reinterpret_cast<float4*>(out)[i] = s;
    }
}

// ---------- launch ----------
extern "C" void kernel_launch(void* const* d_in, const int* in_sizes, int n_in,
                              void* d_out, int out_size) {
    const float* X  = (const float*)d_in[0];   // node_feats [S, G*B, C]
    const float* W  = (const float*)d_in[1];   // weight [P, C]
    const float* sf = (const float*)d_in[2];   // smooth_factor [P]
    float* out = (float*)d_out;                // [outputs (G,P,C) | assign (N,P)]
    float* assign_out = out + OUT_ELEMS;

    prep_kernel<<<1, 64>>>(W, sf);
    assign_kernel<<<N / BM, 128>>>(X, W, assign_out);
    gemm2_kernel<<<dim3(C / BC2, G, KS), 128>>>(X, assign_out);
    reduce_kernel<<<(OUT_ELEMS / 4 + 255) / 256, 256>>>(out);
}

// round 3
// speedup vs baseline: 1.8447x; 1.8447x over previous
#include <cuda_runtime.h>

typedef unsigned long long ULL;

// ---------- packed f32x2 helpers (Blackwell sm_103a) ----------
__device__ __forceinline__ ULL f2x2_fma(ULL a, ULL b, ULL c) {
    ULL d;
    asm("fma.rn.f32x2 %0, %1, %2, %3;" : "=l"(d) : "l"(a), "l"(b), "l"(c));
    return d;
}
__device__ __forceinline__ ULL f2x2_dup(float x) {
    ULL p;
    asm("mov.b64 %0, {%1, %2};" : "=l"(p) : "f"(x), "f"(x));
    return p;
}
__device__ __forceinline__ void f2x2_unpack(ULL v, float& lo, float& hi) {
    asm("mov.b64 {%0, %1}, %2;" : "=f"(lo), "=f"(hi) : "l"(v));
}

// ---------- problem constants (fixed instance) ----------
constexpr int S = 3, G = 8, B = 2048, C = 512, P = 64;
constexpr int N = S * G * B;              // 49152
constexpr int OUT_ELEMS = G * P * C;      // 262144
constexpr int KTOT = S * B;               // 6144 rows per graph
constexpr int KS = 14;                    // split-K for GEMM2
constexpr int KCHUNK = 448;               // 14*448 >= 6144, multiple of 16

// ---------- device scratch (no allocations allowed) ----------
__device__ float g_csq[P];
__device__ float g_ivb[P];
__device__ float g_partial[(size_t)KS * OUT_ELEMS];

// ---------- prep: |c|^2 and 1/beta ----------
__global__ void prep_kernel(const float* __restrict__ W, const float* __restrict__ sf) {
    int p = threadIdx.x;
    if (p >= P) return;
    const float4* wr = reinterpret_cast<const float4*>(W + (size_t)p * C);
    float s = 0.f;
#pragma unroll 8
    for (int i = 0; i < C / 4; i++) {
        float4 v = wr[i];
        s += v.x * v.x + v.y * v.y + v.z * v.z + v.w * v.w;
    }
    g_csq[p] = s;
    g_ivb[p] = 1.0f + __expf(-sf[p]);   // 1/sigmoid(sf)
}

// ---------- fused GEMM1 + softmax -> assign [N, P] ----------
constexpr int BM = 128;       // rows per block
constexpr int KC = 16;        // k per stage
constexpr int NSTG = C / KC;  // 32

__global__ __launch_bounds__(128, 3) void assign_kernel(
    const float* __restrict__ X, const float* __restrict__ W,
    float* __restrict__ assign_out)
{
    __shared__ __align__(16) float As[2][KC][BM];   // 16 KB
    __shared__ __align__(16) float Ws[2][KC][P];    // 8 KB
    __shared__ float Xsq[BM];
    __shared__ float Csq[P];
    __shared__ float Ivb[P];

    const int t = threadIdx.x;
    const int row_base = blockIdx.x * BM;
    const int r0 = (t >> 3) * 8;   // 8 rows (4 f32x2 row-pairs)
    const int c0 = (t & 7) * 8;    // 8 cols
    const int wp = t & 63;         // p index owned for W loads
    const int wh = t >> 6;         // which 8 of the 16 k's

    if (t < P) { Csq[t] = g_csq[t]; Ivb[t] = g_ivb[t]; }

    const float* xrow = X + (size_t)(row_base + t) * C;   // thread t owns row t
    const float* wrow = W + (size_t)wp * C + wh * 8;

    ULL acc[4][8];
#pragma unroll
    for (int i = 0; i < 4; i++)
#pragma unroll
        for (int j = 0; j < 8; j++) acc[i][j] = 0ull;

    float xsq = 0.f;
    float4 al[4], wl[2];

    // prologue: stage 0 global loads + smem store
#pragma unroll
    for (int i = 0; i < 4; i++) al[i] = *reinterpret_cast<const float4*>(xrow + i * 4);
    wl[0] = *reinterpret_cast<const float4*>(wrow);
    wl[1] = *reinterpret_cast<const float4*>(wrow + 4);
#pragma unroll
    for (int i = 0; i < 4; i++) {
        As[0][i * 4 + 0][t] = al[i].x; As[0][i * 4 + 1][t] = al[i].y;
        As[0][i * 4 + 2][t] = al[i].z; As[0][i * 4 + 3][t] = al[i].w;
        xsq += al[i].x * al[i].x + al[i].y * al[i].y + al[i].z * al[i].z + al[i].w * al[i].w;
    }
#pragma unroll
    for (int h = 0; h < 2; h++) {
        Ws[0][wh * 8 + h * 4 + 0][wp] = wl[h].x;
        Ws[0][wh * 8 + h * 4 + 1][wp] = wl[h].y;
        Ws[0][wh * 8 + h * 4 + 2][wp] = wl[h].z;
        Ws[0][wh * 8 + h * 4 + 3][wp] = wl[h].w;
    }
    __syncthreads();

#pragma unroll 1
    for (int s = 0; s < NSTG; s++) {
        const int buf = s & 1;
        if (s + 1 < NSTG) {
            const int k0 = (s + 1) * KC;
#pragma unroll
            for (int i = 0; i < 4; i++)
                al[i] = *reinterpret_cast<const float4*>(xrow + k0 + i * 4);
            wl[0] = *reinterpret_cast<const float4*>(wrow + k0);
            wl[1] = *reinterpret_cast<const float4*>(wrow + k0 + 4);
        }
#pragma unroll
        for (int kk = 0; kk < KC; kk++) {
            ulonglong2 a01 = *reinterpret_cast<const ulonglong2*>(&As[buf][kk][r0]);
            ulonglong2 a23 = *reinterpret_cast<const ulonglong2*>(&As[buf][kk][r0 + 4]);
            float4 b0 = *reinterpret_cast<const float4*>(&Ws[buf][kk][c0]);
            float4 b1 = *reinterpret_cast<const float4*>(&Ws[buf][kk][c0 + 4]);
            ULL bd[8];
            bd[0] = f2x2_dup(b0.x); bd[1] = f2x2_dup(b0.y);
            bd[2] = f2x2_dup(b0.z); bd[3] = f2x2_dup(b0.w);
            bd[4] = f2x2_dup(b1.x); bd[5] = f2x2_dup(b1.y);
            bd[6] = f2x2_dup(b1.z); bd[7] = f2x2_dup(b1.w);
            ULL av[4] = {a01.x, a01.y, a23.x, a23.y};
#pragma unroll
            for (int i = 0; i < 4; i++)
#pragma unroll
                for (int j = 0; j < 8; j++)
                    acc[i][j] = f2x2_fma(av[i], bd[j], acc[i][j]);
        }
        if (s + 1 < NSTG) {
            const int nb = buf ^ 1;
#pragma unroll
            for (int i = 0; i < 4; i++) {
                As[nb][i * 4 + 0][t] = al[i].x; As[nb][i * 4 + 1][t] = al[i].y;
                As[nb][i * 4 + 2][t] = al[i].z; As[nb][i * 4 + 3][t] = al[i].w;
                xsq += al[i].x * al[i].x + al[i].y * al[i].y + al[i].z * al[i].z + al[i].w * al[i].w;
            }
#pragma unroll
            for (int h = 0; h < 2; h++) {
                Ws[nb][wh * 8 + h * 4 + 0][wp] = wl[h].x;
                Ws[nb][wh * 8 + h * 4 + 1][wp] = wl[h].y;
                Ws[nb][wh * 8 + h * 4 + 2][wp] = wl[h].z;
                Ws[nb][wh * 8 + h * 4 + 3][wp] = wl[h].w;
            }
        }
        __syncthreads();
    }

    Xsq[t] = xsq;
    __syncthreads();

    // ---- epilogue: softmax from registers, 2 rows at a time (low reg pressure) ----
    float csq_j[8], ivb_j[8];
#pragma unroll
    for (int j = 0; j < 8; j++) { csq_j[j] = Csq[c0 + j]; ivb_j[j] = Ivb[c0 + j]; }

#pragma unroll
    for (int i = 0; i < 4; i++) {
        float e0[8], e1[8];
        const float xs0 = Xsq[r0 + 2 * i];
        const float xs1 = Xsq[r0 + 2 * i + 1];
#pragma unroll
        for (int j = 0; j < 8; j++) {
            float lo, hi;
            f2x2_unpack(acc[i][j], lo, hi);
            e0[j] = fminf(2.f * lo - xs0 - csq_j[j], 0.f) * ivb_j[j];
            e1[j] = fminf(2.f * hi - xs1 - csq_j[j], 0.f) * ivb_j[j];
        }
#pragma unroll
        for (int half = 0; half < 2; half++) {
            float* e = half ? e1 : e0;
            float m = e[0];
#pragma unroll
            for (int j = 1; j < 8; j++) m = fmaxf(m, e[j]);
            m = fmaxf(m, __shfl_xor_sync(0xffffffffu, m, 1));
            m = fmaxf(m, __shfl_xor_sync(0xffffffffu, m, 2));
            m = fmaxf(m, __shfl_xor_sync(0xffffffffu, m, 4));
            float sum = 0.f;
#pragma unroll
            for (int j = 0; j < 8; j++) { float ex = __expf(e[j] - m); e[j] = ex; sum += ex; }
            sum += __shfl_xor_sync(0xffffffffu, sum, 1);
            sum += __shfl_xor_sync(0xffffffffu, sum, 2);
            sum += __shfl_xor_sync(0xffffffffu, sum, 4);
            const float inv = 1.f / sum;
            float* orow = assign_out + (size_t)(row_base + r0 + 2 * i + half) * P + c0;
            *reinterpret_cast<float4*>(orow)     = make_float4(e[0] * inv, e[1] * inv, e[2] * inv, e[3] * inv);
            *reinterpret_cast<float4*>(orow + 4) = make_float4(e[4] * inv, e[5] * inv, e[6] * inv, e[7] * inv);
        }
    }
}

// ---------- GEMM2: out[g] = assign_g^T @ feats_g  (split-K partials) ----------
constexpr int BC2 = 128;
constexpr int KC2 = 16;
constexpr int NST2 = KCHUNK / KC2;   // 28

__global__ __launch_bounds__(128, 3) void gemm2_kernel(
    const float* __restrict__ X, const float* __restrict__ Asn)
{
    __shared__ __align__(16) float Asm[2][KC2][P];     // 8 KB
    __shared__ __align__(16) float Fsm[2][KC2][BC2];   // 16 KB

    const int t = threadIdx.x;
    const int ct = blockIdx.x;   // c tile 0..3
    const int g  = blockIdx.y;   // graph 0..7
    const int ks = blockIdx.z;   // k split 0..KS-1

    const int p0 = (t >> 4) * 8;   // 8 p rows
    const int c0 = (t & 15) * 8;   // 8 cols = 4 f32x2 col-pairs

    const int jj = t >> 3;         // k-row within stage (0..15)
    const int part = t & 7;        // chunk within row

    const int j0 = ks * KCHUNK;
    const int cbase = ct * BC2;

    ULL acc[8][4];
#pragma unroll
    for (int i = 0; i < 8; i++)
#pragma unroll
        for (int j = 0; j < 4; j++) acc[i][j] = 0ull;

    float4 aa[2], ff[4];

    auto load_stage = [&](int stg) {
        const int j = j0 + stg * KC2 + jj;
        if (j < KTOT) {
            const int sidx = j >> 11;            // / B (2048)
            const int n = j & (B - 1);
            const size_t row = (size_t)sidx * (G * B) + (size_t)g * B + n;
            const float* ap = Asn + row * P + part * 8;
            const float* fp = X + row * C + cbase + part * 16;
            aa[0] = *reinterpret_cast<const float4*>(ap);
            aa[1] = *reinterpret_cast<const float4*>(ap + 4);
#pragma unroll
            for (int i = 0; i < 4; i++)
                ff[i] = *reinterpret_cast<const float4*>(fp + 4 * i);
        } else {
            aa[0] = aa[1] = make_float4(0.f, 0.f, 0.f, 0.f);
#pragma unroll
            for (int i = 0; i < 4; i++) ff[i] = make_float4(0.f, 0.f, 0.f, 0.f);
        }
    };
    auto store_stage = [&](int nb) {
        *reinterpret_cast<float4*>(&Asm[nb][jj][part * 8])     = aa[0];
        *reinterpret_cast<float4*>(&Asm[nb][jj][part * 8 + 4]) = aa[1];
#pragma unroll
        for (int i = 0; i < 4; i++)
            *reinterpret_cast<float4*>(&Fsm[nb][jj][part * 16 + 4 * i]) = ff[i];
    };

    load_stage(0);
    store_stage(0);
    __syncthreads();

#pragma unroll 1
    for (int s = 0; s < NST2; s++) {
        const int buf = s & 1;
        if (s + 1 < NST2) load_stage(s + 1);
#pragma unroll
        for (int kk = 0; kk < KC2; kk++) {
            float4 a0 = *reinterpret_cast<const float4*>(&Asm[buf][kk][p0]);
            float4 a1 = *reinterpret_cast<const float4*>(&Asm[buf][kk][p0 + 4]);
            ULL ad[8];
            ad[0] = f2x2_dup(a0.x); ad[1] = f2x2_dup(a0.y);
            ad[2] = f2x2_dup(a0.z); ad[3] = f2x2_dup(a0.w);
            ad[4] = f2x2_dup(a1.x); ad[5] = f2x2_dup(a1.y);
            ad[6] = f2x2_dup(a1.z); ad[7] = f2x2_dup(a1.w);
            ulonglong2 b01 = *reinterpret_cast<const ulonglong2*>(&Fsm[buf][kk][c0]);
            ulonglong2 b23 = *reinterpret_cast<const ulonglong2*>(&Fsm[buf][kk][c0 + 4]);
            ULL bv[4] = {b01.x, b01.y, b23.x, b23.y};
#pragma unroll
            for (int i = 0; i < 8; i++)
#pragma unroll
                for (int j = 0; j < 4; j++)
                    acc[i][j] = f2x2_fma(ad[i], bv[j], acc[i][j]);
        }
        if (s + 1 < NST2) store_stage(buf ^ 1);
        __syncthreads();
    }

    float* dst = g_partial + ((size_t)ks * G + g) * (size_t)(P * C);
#pragma unroll
    for (int i = 0; i < 8; i++) {
        const int p = p0 + i;
        float* drow = dst + (size_t)p * C + cbase + c0;
        ulonglong2 v0; v0.x = acc[i][0]; v0.y = acc[i][1];
        ulonglong2 v1; v1.x = acc[i][2]; v1.y = acc[i][3];
        *reinterpret_cast<ulonglong2*>(drow)     = v0;
        *reinterpret_cast<ulonglong2*>(drow + 4) = v1;
    }
}

// ---------- deterministic split-K reduction (vectorized) ----------
__global__ void reduce_kernel(float* __restrict__ out) {
    const int i = blockIdx.x * blockDim.x + threadIdx.x;
    if (i < OUT_ELEMS / 4) {
        const float4* src = reinterpret_cast<const float4*>(g_partial);
        float4 s = src[i];
#pragma unroll
        for (int ks = 1; ks < KS; ks++) {
            float4 v = src[(size_t)ks * (OUT_ELEMS / 4) + i];
            s.x += v.x; s.y += v.y; s.z += v.z; s.w += v.w;
        }
        reinterpret_cast<float4*>(out)[i] = s;
    }
}

// ---------- launch ----------
extern "C" void kernel_launch(void* const* d_in, const int* in_sizes, int n_in,
                              void* d_out, int out_size) {
    const float* X  = (const float*)d_in[0];   // node_feats [S, G*B, C]
    const float* W  = (const float*)d_in[1];   // weight [P, C]
    const float* sf = (const float*)d_in[2];   // smooth_factor [P]
    float* out = (float*)d_out;                // [outputs (G,P,C) | assign (N,P)]
    float* assign_out = out + OUT_ELEMS;

    prep_kernel<<<1, 64>>>(W, sf);
    assign_kernel<<<N / BM, 128>>>(X, W, assign_out);
    gemm2_kernel<<<dim3(C / BC2, G, KS), 128>>>(X, assign_out);
    reduce_kernel<<<(OUT_ELEMS / 4 + 255) / 256, 256>>>(out);
}

// round 6
// speedup vs baseline: 2.2290x; 1.2084x over previous
#include <cuda_runtime.h>
#include <cuda_bf16.h>
#include <cstdint>

typedef unsigned long long ULL;

// ---------- packed f32x2 helpers (Blackwell sm_103a) ----------
__device__ __forceinline__ ULL f2x2_fma(ULL a, ULL b, ULL c) {
    ULL d;
    asm("fma.rn.f32x2 %0, %1, %2, %3;" : "=l"(d) : "l"(a), "l"(b), "l"(c));
    return d;
}
__device__ __forceinline__ ULL f2x2_dup(float x) {
    ULL p;
    asm("mov.b64 %0, {%1, %2};" : "=l"(p) : "f"(x), "f"(x));
    return p;
}
__device__ __forceinline__ void f2x2_unpack(ULL v, float& lo, float& hi) {
    asm("mov.b64 {%0, %1}, %2;" : "=f"(lo), "=f"(hi) : "l"(v));
}

// ---------- problem constants (fixed instance) ----------
constexpr int S = 3, G = 8, B = 2048, C = 512, P = 64;
constexpr int N = S * G * B;              // 49152
constexpr int OUT_ELEMS = G * P * C;      // 262144
constexpr int KS = 8;                     // split-K for GEMM2
constexpr int KCHUNK = 768;               // 8*768 == 6144 exactly
constexpr int NS2 = KCHUNK / 16;          // 48 stages of k=16

// ---------- device scratch (no allocations allowed) ----------
__device__ float g_csq[P];
__device__ float g_ivb[P];
__device__ float g_partial[(size_t)KS * OUT_ELEMS];

// ---------- small helpers ----------
__device__ __forceinline__ uint32_t smem_u32(const void* p) {
    uint32_t a;
    asm("{ .reg .u64 t; cvta.to.shared.u64 t, %1; cvt.u32.u64 %0, t; }" : "=r"(a) : "l"(p));
    return a;
}
// split fp32 pair -> bf16x2 hi + bf16x2 lo (hi is truncated-top-16-ish via rn)
__device__ __forceinline__ void bfsplit2(float f0, float f1, uint32_t& ph, uint32_t& pl) {
    asm("cvt.rn.bf16x2.f32 %0, %1, %2;" : "=r"(ph) : "f"(f1), "f"(f0));
    float h0 = __uint_as_float(ph << 16);
    float h1 = __uint_as_float(ph & 0xFFFF0000u);
    float l0 = f0 - h0, l1 = f1 - h1;
    asm("cvt.rn.bf16x2.f32 %0, %1, %2;" : "=r"(pl) : "f"(l1), "f"(l0));
}
__device__ __forceinline__ void mma16816(float* d, const uint32_t* a, const uint32_t* b) {
    asm volatile(
        "mma.sync.aligned.m16n8k16.row.col.f32.bf16.bf16.f32 "
        "{%0,%1,%2,%3}, {%4,%5,%6,%7}, {%8,%9}, {%0,%1,%2,%3};"
        : "+f"(d[0]), "+f"(d[1]), "+f"(d[2]), "+f"(d[3])
        : "r"(a[0]), "r"(a[1]), "r"(a[2]), "r"(a[3]), "r"(b[0]), "r"(b[1]));
}
__device__ __forceinline__ void ldmx2t(uint32_t& r0, uint32_t& r1, uint32_t addr) {
    asm volatile("ldmatrix.sync.aligned.m8n8.x2.trans.shared.b16 {%0,%1}, [%2];"
                 : "=r"(r0), "=r"(r1) : "r"(addr));
}

// ---------- prep: |c|^2 and 1/beta ----------
__global__ void prep_kernel(const float* __restrict__ W, const float* __restrict__ sf) {
    int p = threadIdx.x;
    if (p >= P) return;
    const float4* wr = reinterpret_cast<const float4*>(W + (size_t)p * C);
    float s = 0.f;
#pragma unroll 8
    for (int i = 0; i < C / 4; i++) {
        float4 v = wr[i];
        s += v.x * v.x + v.y * v.y + v.z * v.z + v.w * v.w;
    }
    g_csq[p] = s;
    g_ivb[p] = 1.0f + __expf(-sf[p]);   // 1/sigmoid(sf)
}

// ---------- fused GEMM1 + softmax -> assign [N, P] (SIMT f32x2, R3 proven) ----------
constexpr int BM = 128;
constexpr int KC = 16;
constexpr int NSTG = C / KC;

__global__ __launch_bounds__(128, 3) void assign_kernel(
    const float* __restrict__ X, const float* __restrict__ W,
    float* __restrict__ assign_out)
{
    __shared__ __align__(16) float As[2][KC][BM];
    __shared__ __align__(16) float Ws[2][KC][P];
    __shared__ float Xsq[BM];
    __shared__ float Csq[P];
    __shared__ float Ivb[P];

    const int t = threadIdx.x;
    const int row_base = blockIdx.x * BM;
    const int r0 = (t >> 3) * 8;
    const int c0 = (t & 7) * 8;
    const int wp = t & 63;
    const int wh = t >> 6;

    if (t < P) { Csq[t] = g_csq[t]; Ivb[t] = g_ivb[t]; }

    const float* xrow = X + (size_t)(row_base + t) * C;
    const float* wrow = W + (size_t)wp * C + wh * 8;

    ULL acc[4][8];
#pragma unroll
    for (int i = 0; i < 4; i++)
#pragma unroll
        for (int j = 0; j < 8; j++) acc[i][j] = 0ull;

    float xsq = 0.f;
    float4 al[4], wl[2];

#pragma unroll
    for (int i = 0; i < 4; i++) al[i] = *reinterpret_cast<const float4*>(xrow + i * 4);
    wl[0] = *reinterpret_cast<const float4*>(wrow);
    wl[1] = *reinterpret_cast<const float4*>(wrow + 4);
#pragma unroll
    for (int i = 0; i < 4; i++) {
        As[0][i * 4 + 0][t] = al[i].x; As[0][i * 4 + 1][t] = al[i].y;
        As[0][i * 4 + 2][t] = al[i].z; As[0][i * 4 + 3][t] = al[i].w;
        xsq += al[i].x * al[i].x + al[i].y * al[i].y + al[i].z * al[i].z + al[i].w * al[i].w;
    }
#pragma unroll
    for (int h = 0; h < 2; h++) {
        Ws[0][wh * 8 + h * 4 + 0][wp] = wl[h].x;
        Ws[0][wh * 8 + h * 4 + 1][wp] = wl[h].y;
        Ws[0][wh * 8 + h * 4 + 2][wp] = wl[h].z;
        Ws[0][wh * 8 + h * 4 + 3][wp] = wl[h].w;
    }
    __syncthreads();

#pragma unroll 1
    for (int s = 0; s < NSTG; s++) {
        const int buf = s & 1;
        if (s + 1 < NSTG) {
            const int k0 = (s + 1) * KC;
#pragma unroll
            for (int i = 0; i < 4; i++)
                al[i] = *reinterpret_cast<const float4*>(xrow + k0 + i * 4);
            wl[0] = *reinterpret_cast<const float4*>(wrow + k0);
            wl[1] = *reinterpret_cast<const float4*>(wrow + k0 + 4);
        }
#pragma unroll
        for (int kk = 0; kk < KC; kk++) {
            ulonglong2 a01 = *reinterpret_cast<const ulonglong2*>(&As[buf][kk][r0]);
            ulonglong2 a23 = *reinterpret_cast<const ulonglong2*>(&As[buf][kk][r0 + 4]);
            float4 b0 = *reinterpret_cast<const float4*>(&Ws[buf][kk][c0]);
            float4 b1 = *reinterpret_cast<const float4*>(&Ws[buf][kk][c0 + 4]);
            ULL bd[8];
            bd[0] = f2x2_dup(b0.x); bd[1] = f2x2_dup(b0.y);
            bd[2] = f2x2_dup(b0.z); bd[3] = f2x2_dup(b0.w);
            bd[4] = f2x2_dup(b1.x); bd[5] = f2x2_dup(b1.y);
            bd[6] = f2x2_dup(b1.z); bd[7] = f2x2_dup(b1.w);
            ULL av[4] = {a01.x, a01.y, a23.x, a23.y};
#pragma unroll
            for (int i = 0; i < 4; i++)
#pragma unroll
                for (int j = 0; j < 8; j++)
                    acc[i][j] = f2x2_fma(av[i], bd[j], acc[i][j]);
        }
        if (s + 1 < NSTG) {
            const int nb = buf ^ 1;
#pragma unroll
            for (int i = 0; i < 4; i++) {
                As[nb][i * 4 + 0][t] = al[i].x; As[nb][i * 4 + 1][t] = al[i].y;
                As[nb][i * 4 + 2][t] = al[i].z; As[nb][i * 4 + 3][t] = al[i].w;
                xsq += al[i].x * al[i].x + al[i].y * al[i].y + al[i].z * al[i].z + al[i].w * al[i].w;
            }
#pragma unroll
            for (int h = 0; h < 2; h++) {
                Ws[nb][wh * 8 + h * 4 + 0][wp] = wl[h].x;
                Ws[nb][wh * 8 + h * 4 + 1][wp] = wl[h].y;
                Ws[nb][wh * 8 + h * 4 + 2][wp] = wl[h].z;
                Ws[nb][wh * 8 + h * 4 + 3][wp] = wl[h].w;
            }
        }
        __syncthreads();
    }

    Xsq[t] = xsq;
    __syncthreads();

    float csq_j[8], ivb_j[8];
#pragma unroll
    for (int j = 0; j < 8; j++) { csq_j[j] = Csq[c0 + j]; ivb_j[j] = Ivb[c0 + j]; }

#pragma unroll
    for (int i = 0; i < 4; i++) {
        float e0[8], e1[8];
        const float xs0 = Xsq[r0 + 2 * i];
        const float xs1 = Xsq[r0 + 2 * i + 1];
#pragma unroll
        for (int j = 0; j < 8; j++) {
            float lo, hi;
            f2x2_unpack(acc[i][j], lo, hi);
            e0[j] = fminf(2.f * lo - xs0 - csq_j[j], 0.f) * ivb_j[j];
            e1[j] = fminf(2.f * hi - xs1 - csq_j[j], 0.f) * ivb_j[j];
        }
#pragma unroll
        for (int half = 0; half < 2; half++) {
            float* e = half ? e1 : e0;
            float m = e[0];
#pragma unroll
            for (int j = 1; j < 8; j++) m = fmaxf(m, e[j]);
            m = fmaxf(m, __shfl_xor_sync(0xffffffffu, m, 1));
            m = fmaxf(m, __shfl_xor_sync(0xffffffffu, m, 2));
            m = fmaxf(m, __shfl_xor_sync(0xffffffffu, m, 4));
            float sum = 0.f;
#pragma unroll
            for (int j = 0; j < 8; j++) { float ex = __expf(e[j] - m); e[j] = ex; sum += ex; }
            sum += __shfl_xor_sync(0xffffffffu, sum, 1);
            sum += __shfl_xor_sync(0xffffffffu, sum, 2);
            sum += __shfl_xor_sync(0xffffffffu, sum, 4);
            const float inv = 1.f / sum;
            float* orow = assign_out + (size_t)(row_base + r0 + 2 * i + half) * P + c0;
            *reinterpret_cast<float4*>(orow)     = make_float4(e[0] * inv, e[1] * inv, e[2] * inv, e[3] * inv);
            *reinterpret_cast<float4*>(orow + 4) = make_float4(e[4] * inv, e[5] * inv, e[6] * inv, e[7] * inv);
        }
    }
}

// ---------- GEMM2 on HMMA (mma.sync bf16, split x3) ----------
// per CTA: D[p=64][c=64] for (ct, gg, ks);  A = assign^T [p][k], B = feats [k][c]
constexpr int ASTR = 24;   // halves per A row (48 B)
constexpr int BSTR = 72;   // halves per B row (144 B)

__global__ __launch_bounds__(128) void gemm2_mma(
    const float* __restrict__ X, const float* __restrict__ Asn)
{
    __shared__ __align__(16) __nv_bfloat16 AsH[2][64][ASTR];
    __shared__ __align__(16) __nv_bfloat16 AsL[2][64][ASTR];
    __shared__ __align__(16) __nv_bfloat16 BsH[2][16][BSTR];
    __shared__ __align__(16) __nv_bfloat16 BsL[2][16][BSTR];

    const int t = threadIdx.x;
    const int w = t >> 5;
    const int lane = t & 31;
    const int g8 = lane >> 2;       // mma group id
    const int tid4 = lane & 3;      // thread in group

    const int ct = blockIdx.x;      // c tile 0..7
    const int gg = blockIdx.y;      // graph 0..7
    const int ks = blockIdx.z;      // split 0..KS-1
    const int cbase = ct * 64;
    const int jbase0 = ks * KCHUNK;

    // loader roles
    const int ap = t & 63;          // assign loader: p column
    const int akh = t >> 6;         // which 8 k's (0/1)
    const int xk = t >> 3;          // X loader: k row (0..15)
    const int xc = (t & 7) * 8;     // 8 c's

    const uint32_t bshH = smem_u32(&BsH[0][0][0]);
    const uint32_t bshL = smem_u32(&BsL[0][0][0]);
    const int lrow = lane & 15;     // ldmatrix row provider

    float acc[4][2][4];
#pragma unroll
    for (int mi = 0; mi < 4; mi++)
#pragma unroll
        for (int ni = 0; ni < 2; ni++)
#pragma unroll
            for (int q = 0; q < 4; q++) acc[mi][ni][q] = 0.f;

    float a_st[8];
    float4 xv0, xv1;

    auto gl_load = [&](int s) {
        const int jb = jbase0 + s * 16;
        {
            const int j = jb + akh * 8;
            // 16-row chunk never straddles a 2048 boundary (all offsets mult of 8/16)
            const size_t base = (size_t)(j >> 11) * (G * B) + (size_t)gg * B + (j & 2047);
#pragma unroll
            for (int i = 0; i < 8; i++)
                a_st[i] = Asn[(base + i) * P + ap];
        }
        {
            const int j = jb + xk;
            const size_t row = (size_t)(j >> 11) * (G * B) + (size_t)gg * B + (j & 2047);
            const float* xp = X + row * C + cbase + xc;
            xv0 = *reinterpret_cast<const float4*>(xp);
            xv1 = *reinterpret_cast<const float4*>(xp + 4);
        }
    };
    auto st_stage = [&](int b) {
        uint32_t h[4], l[4];
        bfsplit2(a_st[0], a_st[1], h[0], l[0]);
        bfsplit2(a_st[2], a_st[3], h[1], l[1]);
        bfsplit2(a_st[4], a_st[5], h[2], l[2]);
        bfsplit2(a_st[6], a_st[7], h[3], l[3]);
        *reinterpret_cast<uint4*>(&AsH[b][ap][akh * 8]) = make_uint4(h[0], h[1], h[2], h[3]);
        *reinterpret_cast<uint4*>(&AsL[b][ap][akh * 8]) = make_uint4(l[0], l[1], l[2], l[3]);
        bfsplit2(xv0.x, xv0.y, h[0], l[0]);
        bfsplit2(xv0.z, xv0.w, h[1], l[1]);
        bfsplit2(xv1.x, xv1.y, h[2], l[2]);
        bfsplit2(xv1.z, xv1.w, h[3], l[3]);
        *reinterpret_cast<uint4*>(&BsH[b][xk][xc]) = make_uint4(h[0], h[1], h[2], h[3]);
        *reinterpret_cast<uint4*>(&BsL[b][xk][xc]) = make_uint4(l[0], l[1], l[2], l[3]);
    };

    gl_load(0);
    st_stage(0);
    __syncthreads();

#pragma unroll 1
    for (int s = 0; s < NS2; s++) {
        const int b = s & 1;
        if (s + 1 < NS2) gl_load(s + 1);

        // B fragments (ldmatrix x2 trans), n strip for this warp = w*16 + ni*8
        uint32_t bh[2][2], bl[2][2];
#pragma unroll
        for (int ni = 0; ni < 2; ni++) {
            const uint32_t off =
                (uint32_t)((b * 16 + lrow) * BSTR + (w * 16 + ni * 8)) * 2;
            ldmx2t(bh[ni][0], bh[ni][1], bshH + off);
            ldmx2t(bl[ni][0], bl[ni][1], bshL + off);
        }
#pragma unroll
        for (int mi = 0; mi < 4; mi++) {
            const int r0_ = mi * 16 + g8;
            const int r1_ = r0_ + 8;
            uint32_t ah[4], al_[4];
            ah[0] = *reinterpret_cast<const uint32_t*>(&AsH[b][r0_][2 * tid4]);
            ah[1] = *reinterpret_cast<const uint32_t*>(&AsH[b][r1_][2 * tid4]);
            ah[2] = *reinterpret_cast<const uint32_t*>(&AsH[b][r0_][8 + 2 * tid4]);
            ah[3] = *reinterpret_cast<const uint32_t*>(&AsH[b][r1_][8 + 2 * tid4]);
            al_[0] = *reinterpret_cast<const uint32_t*>(&AsL[b][r0_][2 * tid4]);
            al_[1] = *reinterpret_cast<const uint32_t*>(&AsL[b][r1_][2 * tid4]);
            al_[2] = *reinterpret_cast<const uint32_t*>(&AsL[b][r0_][8 + 2 * tid4]);
            al_[3] = *reinterpret_cast<const uint32_t*>(&AsL[b][r1_][8 + 2 * tid4]);
#pragma unroll
            for (int ni = 0; ni < 2; ni++) {
                mma16816(acc[mi][ni], ah, bh[ni]);
                mma16816(acc[mi][ni], ah, bl[ni]);
                mma16816(acc[mi][ni], al_, bh[ni]);
            }
        }

        if (s + 1 < NS2) st_stage(b ^ 1);
        __syncthreads();
    }

    // epilogue: D[p][c] -> g_partial
    float* dst = g_partial + ((size_t)ks * G + gg) * (size_t)(P * C);
#pragma unroll
    for (int mi = 0; mi < 4; mi++) {
        const int p0_ = mi * 16 + g8;
#pragma unroll
        for (int ni = 0; ni < 2; ni++) {
            const int cc = cbase + w * 16 + ni * 8 + tid4 * 2;
            *reinterpret_cast<float2*>(dst + (size_t)p0_ * C + cc) =
                make_float2(acc[mi][ni][0], acc[mi][ni][1]);
            *reinterpret_cast<float2*>(dst + (size_t)(p0_ + 8) * C + cc) =
                make_float2(acc[mi][ni][2], acc[mi][ni][3]);
        }
    }
}

// ---------- deterministic split-K reduction (vectorized) ----------
__global__ void reduce_kernel(float* __restrict__ out) {
    const int i = blockIdx.x * blockDim.x + threadIdx.x;
    if (i < OUT_ELEMS / 4) {
        const float4* src = reinterpret_cast<const float4*>(g_partial);
        float4 s = src[i];
#pragma unroll
        for (int ks = 1; ks < KS; ks++) {
            float4 v = src[(size_t)ks * (OUT_ELEMS / 4) + i];
            s.x += v.x; s.y += v.y; s.z += v.z; s.w += v.w;
        }
        reinterpret_cast<float4*>(out)[i] = s;
    }
}

// ---------- launch ----------
extern "C" void kernel_launch(void* const* d_in, const int* in_sizes, int n_in,
                              void* d_out, int out_size) {
    const float* X  = (const float*)d_in[0];   // node_feats [S, G*B, C]
    const float* W  = (const float*)d_in[1];   // weight [P, C]
    const float* sf = (const float*)d_in[2];   // smooth_factor [P]
    float* out = (float*)d_out;                // [outputs (G,P,C) | assign (N,P)]
    float* assign_out = out + OUT_ELEMS;

    prep_kernel<<<1, 64>>>(W, sf);
    assign_kernel<<<N / BM, 128>>>(X, W, assign_out);
    gemm2_mma<<<dim3(C / 64, G, KS), 128>>>(X, assign_out);
    reduce_kernel<<<(OUT_ELEMS / 4 + 255) / 256, 256>>>(out);
}

// round 7
// speedup vs baseline: 2.4526x; 1.1003x over previous
#include <cuda_runtime.h>
#include <cuda_bf16.h>
#include <cstdint>

typedef unsigned long long ULL;

// ---------- problem constants (fixed instance) ----------
constexpr int S = 3, G = 8, B = 2048, C = 512, P = 64;
constexpr int N = S * G * B;              // 49152
constexpr int OUT_ELEMS = G * P * C;      // 262144
constexpr int KS = 8;                     // split-K for GEMM2
constexpr int KCHUNK = 768;               // 8*768 == 6144 exactly
constexpr int NS2 = KCHUNK / 16;          // 48 stages of k=16

// ---------- device scratch (no allocations allowed) ----------
__device__ float g_csq[P];
__device__ float g_ivb[P];
__device__ float g_partial[(size_t)KS * OUT_ELEMS];
__device__ __nv_bfloat16 g_whi[P * C];
__device__ __nv_bfloat16 g_wlo[P * C];

// ---------- small helpers ----------
__device__ __forceinline__ uint32_t smem_u32(const void* p) {
    uint32_t a;
    asm("{ .reg .u64 t; cvta.to.shared.u64 t, %1; cvt.u32.u64 %0, t; }" : "=r"(a) : "l"(p));
    return a;
}
// split fp32 pair -> bf16x2 hi + bf16x2 lo
__device__ __forceinline__ void bfsplit2(float f0, float f1, uint32_t& ph, uint32_t& pl) {
    asm("cvt.rn.bf16x2.f32 %0, %1, %2;" : "=r"(ph) : "f"(f1), "f"(f0));
    float h0 = __uint_as_float(ph << 16);
    float h1 = __uint_as_float(ph & 0xFFFF0000u);
    float l0 = f0 - h0, l1 = f1 - h1;
    asm("cvt.rn.bf16x2.f32 %0, %1, %2;" : "=r"(pl) : "f"(l1), "f"(l0));
}
__device__ __forceinline__ void mma16816(float* d, const uint32_t* a, const uint32_t* b) {
    asm volatile(
        "mma.sync.aligned.m16n8k16.row.col.f32.bf16.bf16.f32 "
        "{%0,%1,%2,%3}, {%4,%5,%6,%7}, {%8,%9}, {%0,%1,%2,%3};"
        : "+f"(d[0]), "+f"(d[1]), "+f"(d[2]), "+f"(d[3])
        : "r"(a[0]), "r"(a[1]), "r"(a[2]), "r"(a[3]), "r"(b[0]), "r"(b[1]));
}
__device__ __forceinline__ void ldmx2t(uint32_t& r0, uint32_t& r1, uint32_t addr) {
    asm volatile("ldmatrix.sync.aligned.m8n8.x2.trans.shared.b16 {%0,%1}, [%2];"
                 : "=r"(r0), "=r"(r1) : "r"(addr));
}
__device__ __forceinline__ void ldmx4(uint32_t* r, uint32_t addr) {
    asm volatile("ldmatrix.sync.aligned.m8n8.x4.shared.b16 {%0,%1,%2,%3}, [%4];"
                 : "=r"(r[0]), "=r"(r[1]), "=r"(r[2]), "=r"(r[3]) : "r"(addr));
}

// ---------- prep: |c|^2, 1/beta, W split to bf16 hi/lo ----------
__global__ void prep_kernel(const float* __restrict__ W, const float* __restrict__ sf) {
    int p = threadIdx.x;
    if (p >= P) return;
    const float* wr = W + (size_t)p * C;
    float s = 0.f;
    uint32_t* whi = reinterpret_cast<uint32_t*>(g_whi + (size_t)p * C);
    uint32_t* wlo = reinterpret_cast<uint32_t*>(g_wlo + (size_t)p * C);
#pragma unroll 4
    for (int k = 0; k < C; k += 2) {
        float f0 = wr[k], f1 = wr[k + 1];
        s += f0 * f0 + f1 * f1;
        uint32_t h, l;
        bfsplit2(f0, f1, h, l);
        whi[k >> 1] = h;
        wlo[k >> 1] = l;
    }
    g_csq[p] = s;
    g_ivb[p] = 1.0f + __expf(-sf[p]);   // 1/sigmoid(sf)
}

// ---------- fused GEMM1 (HMMA split x3) + softmax -> assign [N, P] ----------
constexpr int BM = 128;
constexpr int APAD = 24;   // halves per smem row (48 B): conflict-free ldmatrix

__global__ __launch_bounds__(128) void assign_tc(
    const float* __restrict__ X, float* __restrict__ assign_out)
{
    __shared__ __align__(16) __nv_bfloat16 AsH[2][BM][APAD];  // 12 KB
    __shared__ __align__(16) __nv_bfloat16 AsL[2][BM][APAD];  // 12 KB
    __shared__ __align__(16) __nv_bfloat16 WsH[2][P][APAD];   // 6 KB
    __shared__ __align__(16) __nv_bfloat16 WsL[2][P][APAD];   // 6 KB
    __shared__ float Xsq[BM];
    __shared__ float Csq[P];
    __shared__ float Ivb[P];

    const int t = threadIdx.x;
    const int w = t >> 5;
    const int lane = t & 31;
    const int g8 = lane >> 2;
    const int t4 = lane & 3;
    const int row_base = blockIdx.x * BM;

    if (t < P) { Csq[t] = g_csq[t]; Ivb[t] = g_ivb[t]; }

    // loader roles
    const float* xrow = X + (size_t)(row_base + t) * C;    // thread t owns row t
    const bool wlo_role = t >= 64;
    const int wr = t & 63;
    const __nv_bfloat16* wsrc = (wlo_role ? g_wlo : g_whi) + (size_t)wr * C;

    // ldmatrix lane addressing (within-buffer offsets, bytes)
    const uint32_t aHb = smem_u32(AsH), aLb = smem_u32(AsL);
    const uint32_t wHb = smem_u32(WsH), wLb = smem_u32(WsL);
    const uint32_t aoff = (uint32_t)(w * 32 + (lane & 7) + ((lane >> 3) & 1) * 8) * 48
                        + ((lane >> 4) & 1) * 16;
    const uint32_t boff = (uint32_t)((lane & 7) + ((lane >> 4) & 1) * 8) * 48
                        + ((lane >> 3) & 1) * 16;

    float acc[2][8][4];
#pragma unroll
    for (int mi = 0; mi < 2; mi++)
#pragma unroll
        for (int ni = 0; ni < 8; ni++)
#pragma unroll
            for (int q = 0; q < 4; q++) acc[mi][ni][q] = 0.f;

    float xsq = 0.f;
    float4 xv[4];
    uint4 wv0, wv1;

    auto gl_load = [&](int s) {
        const int k0 = s * 16;
#pragma unroll
        for (int i = 0; i < 4; i++)
            xv[i] = *reinterpret_cast<const float4*>(xrow + k0 + i * 4);
        const uint4* wp = reinterpret_cast<const uint4*>(wsrc + k0);
        wv0 = wp[0];
        wv1 = wp[1];
    };
    auto st_stage = [&](int b) {
        uint32_t h[8], l[8];
        bfsplit2(xv[0].x, xv[0].y, h[0], l[0]);
        bfsplit2(xv[0].z, xv[0].w, h[1], l[1]);
        bfsplit2(xv[1].x, xv[1].y, h[2], l[2]);
        bfsplit2(xv[1].z, xv[1].w, h[3], l[3]);
        bfsplit2(xv[2].x, xv[2].y, h[4], l[4]);
        bfsplit2(xv[2].z, xv[2].w, h[5], l[5]);
        bfsplit2(xv[3].x, xv[3].y, h[6], l[6]);
        bfsplit2(xv[3].z, xv[3].w, h[7], l[7]);
#pragma unroll
        for (int i = 0; i < 4; i++)
            xsq += xv[i].x * xv[i].x + xv[i].y * xv[i].y +
                   xv[i].z * xv[i].z + xv[i].w * xv[i].w;
        *reinterpret_cast<uint4*>(&AsH[b][t][0]) = make_uint4(h[0], h[1], h[2], h[3]);
        *reinterpret_cast<uint4*>(&AsH[b][t][8]) = make_uint4(h[4], h[5], h[6], h[7]);
        *reinterpret_cast<uint4*>(&AsL[b][t][0]) = make_uint4(l[0], l[1], l[2], l[3]);
        *reinterpret_cast<uint4*>(&AsL[b][t][8]) = make_uint4(l[4], l[5], l[6], l[7]);
        if (!wlo_role) {
            *reinterpret_cast<uint4*>(&WsH[b][wr][0]) = wv0;
            *reinterpret_cast<uint4*>(&WsH[b][wr][8]) = wv1;
        } else {
            *reinterpret_cast<uint4*>(&WsL[b][wr][0]) = wv0;
            *reinterpret_cast<uint4*>(&WsL[b][wr][8]) = wv1;
        }
    };

    gl_load(0);
    st_stage(0);
    __syncthreads();

#pragma unroll 1
    for (int s = 0; s < 32; s++) {
        const int b = s & 1;
        if (s + 1 < 32) gl_load(s + 1);

        // B fragments: all 8 ni strips, hi and lo (4 ldmatrix.x4 each)
        uint32_t bh[8][2], bl[8][2];
#pragma unroll
        for (int np = 0; np < 4; np++) {
            uint32_t r[4];
            ldmx4(r, wHb + (uint32_t)b * 3072 + boff + np * 768);
            bh[2 * np][0] = r[0]; bh[2 * np][1] = r[1];
            bh[2 * np + 1][0] = r[2]; bh[2 * np + 1][1] = r[3];
            ldmx4(r, wLb + (uint32_t)b * 3072 + boff + np * 768);
            bl[2 * np][0] = r[0]; bl[2 * np][1] = r[1];
            bl[2 * np + 1][0] = r[2]; bl[2 * np + 1][1] = r[3];
        }
#pragma unroll
        for (int mi = 0; mi < 2; mi++) {
            uint32_t ah[4], al_[4];
            ldmx4(ah, aHb + (uint32_t)b * 6144 + aoff + mi * 768);
            ldmx4(al_, aLb + (uint32_t)b * 6144 + aoff + mi * 768);
#pragma unroll
            for (int ni = 0; ni < 8; ni++) {
                mma16816(acc[mi][ni], ah, bh[ni]);
                mma16816(acc[mi][ni], ah, bl[ni]);
                mma16816(acc[mi][ni], al_, bh[ni]);
            }
        }

        if (s + 1 < 32) st_stage(b ^ 1);
        __syncthreads();
    }

    Xsq[t] = xsq;
    __syncthreads();

    // ---- softmax epilogue from accumulators ----
    float csq_c[16], ivb_c[16];
#pragma unroll
    for (int ni = 0; ni < 8; ni++)
#pragma unroll
        for (int j = 0; j < 2; j++) {
            const int c = ni * 8 + t4 * 2 + j;
            csq_c[2 * ni + j] = Csq[c];
            ivb_c[2 * ni + j] = Ivb[c];
        }

#pragma unroll
    for (int mi = 0; mi < 2; mi++) {
#pragma unroll
        for (int half = 0; half < 2; half++) {
            const int rl = w * 32 + mi * 16 + half * 8 + g8;
            const float xs = Xsq[rl];
            float v[16];
#pragma unroll
            for (int ni = 0; ni < 8; ni++)
#pragma unroll
                for (int j = 0; j < 2; j++)
                    v[2 * ni + j] = fminf(2.f * acc[mi][ni][2 * half + j] - xs - csq_c[2 * ni + j], 0.f)
                                    * ivb_c[2 * ni + j];
            float m = v[0];
#pragma unroll
            for (int q = 1; q < 16; q++) m = fmaxf(m, v[q]);
            m = fmaxf(m, __shfl_xor_sync(0xffffffffu, m, 1));
            m = fmaxf(m, __shfl_xor_sync(0xffffffffu, m, 2));
            float sum = 0.f;
#pragma unroll
            for (int q = 0; q < 16; q++) { float ex = __expf(v[q] - m); v[q] = ex; sum += ex; }
            sum += __shfl_xor_sync(0xffffffffu, sum, 1);
            sum += __shfl_xor_sync(0xffffffffu, sum, 2);
            const float inv = 1.f / sum;
            float* orow = assign_out + (size_t)(row_base + rl) * P + t4 * 2;
#pragma unroll
            for (int ni = 0; ni < 8; ni++)
                *reinterpret_cast<float2*>(orow + ni * 8) =
                    make_float2(v[2 * ni] * inv, v[2 * ni + 1] * inv);
        }
    }
}

// ---------- GEMM2 on HMMA (mma.sync bf16, split x3) — unchanged from R6 ----------
constexpr int ASTR = 24;   // halves per A row (48 B)
constexpr int BSTR = 72;   // halves per B row (144 B)

__global__ __launch_bounds__(128) void gemm2_mma(
    const float* __restrict__ X, const float* __restrict__ Asn)
{
    __shared__ __align__(16) __nv_bfloat16 AsH[2][64][ASTR];
    __shared__ __align__(16) __nv_bfloat16 AsL[2][64][ASTR];
    __shared__ __align__(16) __nv_bfloat16 BsH[2][16][BSTR];
    __shared__ __align__(16) __nv_bfloat16 BsL[2][16][BSTR];

    const int t = threadIdx.x;
    const int w = t >> 5;
    const int lane = t & 31;
    const int g8 = lane >> 2;
    const int tid4 = lane & 3;

    const int ct = blockIdx.x;
    const int gg = blockIdx.y;
    const int ks = blockIdx.z;
    const int cbase = ct * 64;
    const int jbase0 = ks * KCHUNK;

    const int ap = t & 63;
    const int akh = t >> 6;
    const int xk = t >> 3;
    const int xc = (t & 7) * 8;

    const uint32_t bshH = smem_u32(&BsH[0][0][0]);
    const uint32_t bshL = smem_u32(&BsL[0][0][0]);
    const int lrow = lane & 15;

    float acc[4][2][4];
#pragma unroll
    for (int mi = 0; mi < 4; mi++)
#pragma unroll
        for (int ni = 0; ni < 2; ni++)
#pragma unroll
            for (int q = 0; q < 4; q++) acc[mi][ni][q] = 0.f;

    float a_st[8];
    float4 xv0, xv1;

    auto gl_load = [&](int s) {
        const int jb = jbase0 + s * 16;
        {
            const int j = jb + akh * 8;
            const size_t base = (size_t)(j >> 11) * (G * B) + (size_t)gg * B + (j & 2047);
#pragma unroll
            for (int i = 0; i < 8; i++)
                a_st[i] = Asn[(base + i) * P + ap];
        }
        {
            const int j = jb + xk;
            const size_t row = (size_t)(j >> 11) * (G * B) + (size_t)gg * B + (j & 2047);
            const float* xp = X + row * C + cbase + xc;
            xv0 = *reinterpret_cast<const float4*>(xp);
            xv1 = *reinterpret_cast<const float4*>(xp + 4);
        }
    };
    auto st_stage = [&](int b) {
        uint32_t h[4], l[4];
        bfsplit2(a_st[0], a_st[1], h[0], l[0]);
        bfsplit2(a_st[2], a_st[3], h[1], l[1]);
        bfsplit2(a_st[4], a_st[5], h[2], l[2]);
        bfsplit2(a_st[6], a_st[7], h[3], l[3]);
        *reinterpret_cast<uint4*>(&AsH[b][ap][akh * 8]) = make_uint4(h[0], h[1], h[2], h[3]);
        *reinterpret_cast<uint4*>(&AsL[b][ap][akh * 8]) = make_uint4(l[0], l[1], l[2], l[3]);
        bfsplit2(xv0.x, xv0.y, h[0], l[0]);
        bfsplit2(xv0.z, xv0.w, h[1], l[1]);
        bfsplit2(xv1.x, xv1.y, h[2], l[2]);
        bfsplit2(xv1.z, xv1.w, h[3], l[3]);
        *reinterpret_cast<uint4*>(&BsH[b][xk][xc]) = make_uint4(h[0], h[1], h[2], h[3]);
        *reinterpret_cast<uint4*>(&BsL[b][xk][xc]) = make_uint4(l[0], l[1], l[2], l[3]);
    };

    gl_load(0);
    st_stage(0);
    __syncthreads();

#pragma unroll 1
    for (int s = 0; s < NS2; s++) {
        const int b = s & 1;
        if (s + 1 < NS2) gl_load(s + 1);

        uint32_t bh[2][2], bl[2][2];
#pragma unroll
        for (int ni = 0; ni < 2; ni++) {
            const uint32_t off =
                (uint32_t)((b * 16 + lrow) * BSTR + (w * 16 + ni * 8)) * 2;
            ldmx2t(bh[ni][0], bh[ni][1], bshH + off);
            ldmx2t(bl[ni][0], bl[ni][1], bshL + off);
        }
#pragma unroll
        for (int mi = 0; mi < 4; mi++) {
            const int r0_ = mi * 16 + g8;
            const int r1_ = r0_ + 8;
            uint32_t ah[4], al_[4];
            ah[0] = *reinterpret_cast<const uint32_t*>(&AsH[b][r0_][2 * tid4]);
            ah[1] = *reinterpret_cast<const uint32_t*>(&AsH[b][r1_][2 * tid4]);
            ah[2] = *reinterpret_cast<const uint32_t*>(&AsH[b][r0_][8 + 2 * tid4]);
            ah[3] = *reinterpret_cast<const uint32_t*>(&AsH[b][r1_][8 + 2 * tid4]);
            al_[0] = *reinterpret_cast<const uint32_t*>(&AsL[b][r0_][2 * tid4]);
            al_[1] = *reinterpret_cast<const uint32_t*>(&AsL[b][r1_][2 * tid4]);
            al_[2] = *reinterpret_cast<const uint32_t*>(&AsL[b][r0_][8 + 2 * tid4]);
            al_[3] = *reinterpret_cast<const uint32_t*>(&AsL[b][r1_][8 + 2 * tid4]);
#pragma unroll
            for (int ni = 0; ni < 2; ni++) {
                mma16816(acc[mi][ni], ah, bh[ni]);
                mma16816(acc[mi][ni], ah, bl[ni]);
                mma16816(acc[mi][ni], al_, bh[ni]);
            }
        }

        if (s + 1 < NS2) st_stage(b ^ 1);
        __syncthreads();
    }

    float* dst = g_partial + ((size_t)ks * G + gg) * (size_t)(P * C);
#pragma unroll
    for (int mi = 0; mi < 4; mi++) {
        const int p0_ = mi * 16 + g8;
#pragma unroll
        for (int ni = 0; ni < 2; ni++) {
            const int cc = cbase + w * 16 + ni * 8 + tid4 * 2;
            *reinterpret_cast<float2*>(dst + (size_t)p0_ * C + cc) =
                make_float2(acc[mi][ni][0], acc[mi][ni][1]);
            *reinterpret_cast<float2*>(dst + (size_t)(p0_ + 8) * C + cc) =
                make_float2(acc[mi][ni][2], acc[mi][ni][3]);
        }
    }
}

// ---------- deterministic split-K reduction (vectorized) ----------
__global__ void reduce_kernel(float* __restrict__ out) {
    const int i = blockIdx.x * blockDim.x + threadIdx.x;
    if (i < OUT_ELEMS / 4) {
        const float4* src = reinterpret_cast<const float4*>(g_partial);
        float4 s = src[i];
#pragma unroll
        for (int ks = 1; ks < KS; ks++) {
            float4 v = src[(size_t)ks * (OUT_ELEMS / 4) + i];
            s.x += v.x; s.y += v.y; s.z += v.z; s.w += v.w;
        }
        reinterpret_cast<float4*>(out)[i] = s;
    }
}

// ---------- launch ----------
extern "C" void kernel_launch(void* const* d_in, const int* in_sizes, int n_in,
                              void* d_out, int out_size) {
    const float* X  = (const float*)d_in[0];   // node_feats [S, G*B, C]
    const float* W  = (const float*)d_in[1];   // weight [P, C]
    const float* sf = (const float*)d_in[2];   // smooth_factor [P]
    float* out = (float*)d_out;                // [outputs (G,P,C) | assign (N,P)]
    float* assign_out = out + OUT_ELEMS;

    prep_kernel<<<1, 64>>>(W, sf);
    assign_tc<<<N / BM, 128>>>(X, assign_out);
    gemm2_mma<<<dim3(C / 64, G, KS), 128>>>(X, assign_out);
    reduce_kernel<<<(OUT_ELEMS / 4 + 255) / 256, 256>>>(out);
}

// round 8
// speedup vs baseline: 2.8042x; 1.1434x over previous
#include <cuda_runtime.h>
#include <cuda_bf16.h>
#include <cstdint>

// ---------- problem constants (fixed instance) ----------
constexpr int S = 3, G = 8, B = 2048, C = 512, P = 64;
constexpr int N = S * G * B;              // 49152
constexpr int OUT_ELEMS = G * P * C;      // 262144
constexpr int KS = 8;                     // split-K for GEMM2
constexpr int KCHUNK = 768;               // 8*768 == 6144 exactly
constexpr int NS2 = KCHUNK / 16;          // 48 stages of k=16

// ---------- device scratch (no allocations allowed) ----------
__device__ float g_csq[P];
__device__ float g_ivb[P];
__device__ float g_partial[(size_t)KS * OUT_ELEMS];
__device__ __nv_bfloat16 g_whi[P * C];
__device__ __nv_bfloat16 g_wlo[P * C];
__device__ __nv_bfloat16 g_ahi[(size_t)N * P];
__device__ __nv_bfloat16 g_alo[(size_t)N * P];

// ---------- small helpers ----------
__device__ __forceinline__ uint32_t smem_u32(const void* p) {
    uint32_t a;
    asm("{ .reg .u64 t; cvta.to.shared.u64 t, %1; cvt.u32.u64 %0, t; }" : "=r"(a) : "l"(p));
    return a;
}
__device__ __forceinline__ void bfsplit2(float f0, float f1, uint32_t& ph, uint32_t& pl) {
    asm("cvt.rn.bf16x2.f32 %0, %1, %2;" : "=r"(ph) : "f"(f1), "f"(f0));
    float h0 = __uint_as_float(ph << 16);
    float h1 = __uint_as_float(ph & 0xFFFF0000u);
    float l0 = f0 - h0, l1 = f1 - h1;
    asm("cvt.rn.bf16x2.f32 %0, %1, %2;" : "=r"(pl) : "f"(l1), "f"(l0));
}
__device__ __forceinline__ void mma16816(float* d, const uint32_t* a, const uint32_t* b) {
    asm volatile(
        "mma.sync.aligned.m16n8k16.row.col.f32.bf16.bf16.f32 "
        "{%0,%1,%2,%3}, {%4,%5,%6,%7}, {%8,%9}, {%0,%1,%2,%3};"
        : "+f"(d[0]), "+f"(d[1]), "+f"(d[2]), "+f"(d[3])
        : "r"(a[0]), "r"(a[1]), "r"(a[2]), "r"(a[3]), "r"(b[0]), "r"(b[1]));
}
__device__ __forceinline__ void ldmx2t(uint32_t& r0, uint32_t& r1, uint32_t addr) {
    asm volatile("ldmatrix.sync.aligned.m8n8.x2.trans.shared.b16 {%0,%1}, [%2];"
                 : "=r"(r0), "=r"(r1) : "r"(addr));
}
__device__ __forceinline__ void ldmx4(uint32_t* r, uint32_t addr) {
    asm volatile("ldmatrix.sync.aligned.m8n8.x4.shared.b16 {%0,%1,%2,%3}, [%4];"
                 : "=r"(r[0]), "=r"(r[1]), "=r"(r[2]), "=r"(r[3]) : "r"(addr));
}
__device__ __forceinline__ void ldmx4t(uint32_t* r, uint32_t addr) {
    asm volatile("ldmatrix.sync.aligned.m8n8.x4.trans.shared.b16 {%0,%1,%2,%3}, [%4];"
                 : "=r"(r[0]), "=r"(r[1]), "=r"(r[2]), "=r"(r[3]) : "r"(addr));
}

// ---------- prep: |c|^2, 1/beta, W split to bf16 hi/lo ----------
__global__ void prep_kernel(const float* __restrict__ W, const float* __restrict__ sf) {
    int p = threadIdx.x;
    if (p >= P) return;
    const float* wr = W + (size_t)p * C;
    float s = 0.f;
    uint32_t* whi = reinterpret_cast<uint32_t*>(g_whi + (size_t)p * C);
    uint32_t* wlo = reinterpret_cast<uint32_t*>(g_wlo + (size_t)p * C);
#pragma unroll 4
    for (int k = 0; k < C; k += 2) {
        float f0 = wr[k], f1 = wr[k + 1];
        s += f0 * f0 + f1 * f1;
        uint32_t h, l;
        bfsplit2(f0, f1, h, l);
        whi[k >> 1] = h;
        wlo[k >> 1] = l;
    }
    g_csq[p] = s;
    g_ivb[p] = 1.0f + __expf(-sf[p]);   // 1/sigmoid(sf)
}

// ---------- fused GEMM1 (HMMA split x3) + softmax -> assign ----------
constexpr int BM = 128;
constexpr int APAD = 24;   // halves per smem row (48 B)

__global__ __launch_bounds__(128) void assign_tc(
    const float* __restrict__ X, float* __restrict__ assign_out)
{
    __shared__ __align__(16) __nv_bfloat16 AsH[2][BM][APAD];
    __shared__ __align__(16) __nv_bfloat16 AsL[2][BM][APAD];
    __shared__ __align__(16) __nv_bfloat16 WsH[2][P][APAD];
    __shared__ __align__(16) __nv_bfloat16 WsL[2][P][APAD];
    __shared__ float Xsq[BM];
    __shared__ float Csq[P];
    __shared__ float Ivb[P];

    const int t = threadIdx.x;
    const int w = t >> 5;
    const int lane = t & 31;
    const int g8 = lane >> 2;
    const int t4 = lane & 3;
    const int row_base = blockIdx.x * BM;

    if (t < P) { Csq[t] = g_csq[t]; Ivb[t] = g_ivb[t]; }

    // ---- coalesced loader roles ----
    // X: 4 lanes per row; thread covers rows xr, xr+32, xr+64, xr+96, k-quad xq
    const int xr = t >> 2;
    const int xq = t & 3;
    // W: 2 lanes per row from pre-split bf16; rows wr0, wr0+32; chunk wc
    const bool wlo_role = t >= 64;
    const int u = t & 63;
    const int wr0 = u >> 1;
    const int wc = u & 1;
    const __nv_bfloat16* wsrc = wlo_role ? g_wlo : g_whi;

    const uint32_t aHb = smem_u32(AsH), aLb = smem_u32(AsL);
    const uint32_t wHb = smem_u32(WsH), wLb = smem_u32(WsL);
    const uint32_t aoff = (uint32_t)(w * 32 + (lane & 7) + ((lane >> 3) & 1) * 8) * 48
                        + ((lane >> 4) & 1) * 16;
    const uint32_t boff = (uint32_t)((lane & 7) + ((lane >> 4) & 1) * 8) * 48
                        + ((lane >> 3) & 1) * 16;

    float acc[2][8][4];
#pragma unroll
    for (int mi = 0; mi < 2; mi++)
#pragma unroll
        for (int ni = 0; ni < 8; ni++)
#pragma unroll
            for (int q = 0; q < 4; q++) acc[mi][ni][q] = 0.f;

    float xp[4] = {0.f, 0.f, 0.f, 0.f};
    float4 xv[4];
    uint4 wv0, wv1;

    auto gl_load = [&](int s) {
        const int k0 = s * 16;
#pragma unroll
        for (int i = 0; i < 4; i++)
            xv[i] = *reinterpret_cast<const float4*>(
                X + (size_t)(row_base + xr + 32 * i) * C + k0 + xq * 4);
        wv0 = *reinterpret_cast<const uint4*>(wsrc + (size_t)wr0 * C + k0 + wc * 8);
        wv1 = *reinterpret_cast<const uint4*>(wsrc + (size_t)(wr0 + 32) * C + k0 + wc * 8);
    };
    auto st_stage = [&](int b) {
#pragma unroll
        for (int i = 0; i < 4; i++) {
            uint32_t h0, l0, h1, l1;
            bfsplit2(xv[i].x, xv[i].y, h0, l0);
            bfsplit2(xv[i].z, xv[i].w, h1, l1);
            xp[i] += xv[i].x * xv[i].x + xv[i].y * xv[i].y +
                     xv[i].z * xv[i].z + xv[i].w * xv[i].w;
            *reinterpret_cast<uint2*>(&AsH[b][xr + 32 * i][xq * 4]) = make_uint2(h0, h1);
            *reinterpret_cast<uint2*>(&AsL[b][xr + 32 * i][xq * 4]) = make_uint2(l0, l1);
        }
        if (!wlo_role) {
            *reinterpret_cast<uint4*>(&WsH[b][wr0][wc * 8]) = wv0;
            *reinterpret_cast<uint4*>(&WsH[b][wr0 + 32][wc * 8]) = wv1;
        } else {
            *reinterpret_cast<uint4*>(&WsL[b][wr0][wc * 8]) = wv0;
            *reinterpret_cast<uint4*>(&WsL[b][wr0 + 32][wc * 8]) = wv1;
        }
    };

    gl_load(0);
    st_stage(0);
    __syncthreads();

#pragma unroll 1
    for (int s = 0; s < 32; s++) {
        const int b = s & 1;
        if (s + 1 < 32) gl_load(s + 1);

        uint32_t bh[8][2], bl[8][2];
#pragma unroll
        for (int np = 0; np < 4; np++) {
            uint32_t r[4];
            ldmx4(r, wHb + (uint32_t)b * 3072 + boff + np * 768);
            bh[2 * np][0] = r[0]; bh[2 * np][1] = r[1];
            bh[2 * np + 1][0] = r[2]; bh[2 * np + 1][1] = r[3];
            ldmx4(r, wLb + (uint32_t)b * 3072 + boff + np * 768);
            bl[2 * np][0] = r[0]; bl[2 * np][1] = r[1];
            bl[2 * np + 1][0] = r[2]; bl[2 * np + 1][1] = r[3];
        }
#pragma unroll
        for (int mi = 0; mi < 2; mi++) {
            uint32_t ah[4], al_[4];
            ldmx4(ah, aHb + (uint32_t)b * 6144 + aoff + mi * 768);
            ldmx4(al_, aLb + (uint32_t)b * 6144 + aoff + mi * 768);
#pragma unroll
            for (int ni = 0; ni < 8; ni++) {
                mma16816(acc[mi][ni], ah, bh[ni]);
                mma16816(acc[mi][ni], ah, bl[ni]);
                mma16816(acc[mi][ni], al_, bh[ni]);
            }
        }

        if (s + 1 < 32) st_stage(b ^ 1);
        __syncthreads();
    }

    // |x|^2: reduce over the 4-lane quad owning each row
#pragma unroll
    for (int i = 0; i < 4; i++) {
        float sx = xp[i];
        sx += __shfl_xor_sync(0xffffffffu, sx, 1);
        sx += __shfl_xor_sync(0xffffffffu, sx, 2);
        if (xq == 0) Xsq[xr + 32 * i] = sx;
    }
    __syncthreads();

    // ---- softmax epilogue from accumulators ----
    float csq_c[16], ivb_c[16];
#pragma unroll
    for (int ni = 0; ni < 8; ni++)
#pragma unroll
        for (int j = 0; j < 2; j++) {
            const int c = ni * 8 + t4 * 2 + j;
            csq_c[2 * ni + j] = Csq[c];
            ivb_c[2 * ni + j] = Ivb[c];
        }

#pragma unroll
    for (int mi = 0; mi < 2; mi++) {
#pragma unroll
        for (int half = 0; half < 2; half++) {
            const int rl = w * 32 + mi * 16 + half * 8 + g8;
            const float xs = Xsq[rl];
            float v[16];
#pragma unroll
            for (int ni = 0; ni < 8; ni++)
#pragma unroll
                for (int j = 0; j < 2; j++)
                    v[2 * ni + j] = fminf(2.f * acc[mi][ni][2 * half + j] - xs - csq_c[2 * ni + j], 0.f)
                                    * ivb_c[2 * ni + j];
            float m = v[0];
#pragma unroll
            for (int q = 1; q < 16; q++) m = fmaxf(m, v[q]);
            m = fmaxf(m, __shfl_xor_sync(0xffffffffu, m, 1));
            m = fmaxf(m, __shfl_xor_sync(0xffffffffu, m, 2));
            float sum = 0.f;
#pragma unroll
            for (int q = 0; q < 16; q++) { float ex = __expf(v[q] - m); v[q] = ex; sum += ex; }
            sum += __shfl_xor_sync(0xffffffffu, sum, 1);
            sum += __shfl_xor_sync(0xffffffffu, sum, 2);
            const float inv = 1.f / sum;
            const size_t arow = (size_t)(row_base + rl);
            float* orow = assign_out + arow * P + t4 * 2;
            uint32_t* ahp = reinterpret_cast<uint32_t*>(g_ahi) + arow * 32 + t4;
            uint32_t* alp = reinterpret_cast<uint32_t*>(g_alo) + arow * 32 + t4;
#pragma unroll
            for (int ni = 0; ni < 8; ni++) {
                const float a0 = v[2 * ni] * inv, a1 = v[2 * ni + 1] * inv;
                *reinterpret_cast<float2*>(orow + ni * 8) = make_float2(a0, a1);
                uint32_t hh, ll;
                bfsplit2(a0, a1, hh, ll);
                ahp[ni * 4] = hh;
                alp[ni * 4] = ll;
            }
        }
    }
}

// ---------- GEMM2 on HMMA: pre-split assign (bf16), ldmatrix A-frags ----------
constexpr int STR2 = 72;   // halves per smem row (144 B) — conflict-free ldmatrix

__global__ __launch_bounds__(128) void gemm2_mma(const float* __restrict__ X)
{
    __shared__ __align__(16) __nv_bfloat16 AsH[2][16][STR2];
    __shared__ __align__(16) __nv_bfloat16 AsL[2][16][STR2];
    __shared__ __align__(16) __nv_bfloat16 BsH[2][16][STR2];
    __shared__ __align__(16) __nv_bfloat16 BsL[2][16][STR2];

    const int t = threadIdx.x;
    const int w = t >> 5;
    const int lane = t & 31;
    const int g8 = lane >> 2;
    const int tid4 = lane & 3;

    const int ct = blockIdx.x;
    const int gg = blockIdx.y;
    const int ks = blockIdx.z;
    const int cbase = ct * 64;
    const int jbase0 = ks * KCHUNK;

    // loader: krow = k-row in stage, chunk = 8-half chunk
    const int krow = t >> 3;
    const int chunk = t & 7;

    const uint32_t aH = smem_u32(AsH), aL = smem_u32(AsL);
    const uint32_t bH = smem_u32(BsH), bL = smem_u32(BsL);
    // ldmatrix.x4.trans A-frag lane offset (bytes), + p0*2 per mi
    const uint32_t aoffT = (uint32_t)((lane & 7) + ((lane >> 4) & 1) * 8) * (STR2 * 2)
                         + ((lane >> 3) & 1) * 16;
    const int lrow = lane & 15;

    float acc[4][2][4];
#pragma unroll
    for (int mi = 0; mi < 4; mi++)
#pragma unroll
        for (int ni = 0; ni < 2; ni++)
#pragma unroll
            for (int q = 0; q < 4; q++) acc[mi][ni][q] = 0.f;

    uint4 av0, av1;
    float4 xv0, xv1;

    auto gl_load = [&](int s) {
        const int j = jbase0 + s * 16 + krow;
        const size_t row = (size_t)(j >> 11) * (G * B) + (size_t)gg * B + (j & 2047);
        av0 = *reinterpret_cast<const uint4*>(g_ahi + row * P + chunk * 8);
        av1 = *reinterpret_cast<const uint4*>(g_alo + row * P + chunk * 8);
        const float* xp = X + row * C + cbase + chunk * 8;
        xv0 = *reinterpret_cast<const float4*>(xp);
        xv1 = *reinterpret_cast<const float4*>(xp + 4);
    };
    auto st_stage = [&](int b) {
        *reinterpret_cast<uint4*>(&AsH[b][krow][chunk * 8]) = av0;
        *reinterpret_cast<uint4*>(&AsL[b][krow][chunk * 8]) = av1;
        uint32_t h[4], l[4];
        bfsplit2(xv0.x, xv0.y, h[0], l[0]);
        bfsplit2(xv0.z, xv0.w, h[1], l[1]);
        bfsplit2(xv1.x, xv1.y, h[2], l[2]);
        bfsplit2(xv1.z, xv1.w, h[3], l[3]);
        *reinterpret_cast<uint4*>(&BsH[b][krow][chunk * 8]) = make_uint4(h[0], h[1], h[2], h[3]);
        *reinterpret_cast<uint4*>(&BsL[b][krow][chunk * 8]) = make_uint4(l[0], l[1], l[2], l[3]);
    };

    gl_load(0);
    st_stage(0);
    __syncthreads();

#pragma unroll 1
    for (int s = 0; s < NS2; s++) {
        const int b = s & 1;
        if (s + 1 < NS2) gl_load(s + 1);

        // B fragments (c strip for this warp)
        uint32_t bh[2][2], bl[2][2];
#pragma unroll
        for (int ni = 0; ni < 2; ni++) {
            const uint32_t off =
                (uint32_t)((b * 16 + lrow) * STR2 + (w * 16 + ni * 8)) * 2;
            ldmx2t(bh[ni][0], bh[ni][1], bH + off);
            ldmx2t(bl[ni][0], bl[ni][1], bL + off);
        }
#pragma unroll
        for (int mi = 0; mi < 4; mi++) {
            uint32_t ah[4], al_[4];
            const uint32_t ao = (uint32_t)b * (16 * STR2 * 2) + aoffT + mi * 32;
            ldmx4t(ah, aH + ao);
            ldmx4t(al_, aL + ao);
#pragma unroll
            for (int ni = 0; ni < 2; ni++) {
                mma16816(acc[mi][ni], ah, bh[ni]);
                mma16816(acc[mi][ni], ah, bl[ni]);
                mma16816(acc[mi][ni], al_, bh[ni]);
            }
        }

        if (s + 1 < NS2) st_stage(b ^ 1);
        __syncthreads();
    }

    float* dst = g_partial + ((size_t)ks * G + gg) * (size_t)(P * C);
#pragma unroll
    for (int mi = 0; mi < 4; mi++) {
        const int p0_ = mi * 16 + g8;
#pragma unroll
        for (int ni = 0; ni < 2; ni++) {
            const int cc = cbase + w * 16 + ni * 8 + tid4 * 2;
            *reinterpret_cast<float2*>(dst + (size_t)p0_ * C + cc) =
                make_float2(acc[mi][ni][0], acc[mi][ni][1]);
            *reinterpret_cast<float2*>(dst + (size_t)(p0_ + 8) * C + cc) =
                make_float2(acc[mi][ni][2], acc[mi][ni][3]);
        }
    }
}

// ---------- deterministic split-K reduction (vectorized) ----------
__global__ void reduce_kernel(float* __restrict__ out) {
    const int i = blockIdx.x * blockDim.x + threadIdx.x;
    if (i < OUT_ELEMS / 4) {
        const float4* src = reinterpret_cast<const float4*>(g_partial);
        float4 s = src[i];
#pragma unroll
        for (int ks = 1; ks < KS; ks++) {
            float4 v = src[(size_t)ks * (OUT_ELEMS / 4) + i];
            s.x += v.x; s.y += v.y; s.z += v.z; s.w += v.w;
        }
        reinterpret_cast<float4*>(out)[i] = s;
    }
}

// ---------- launch ----------
extern "C" void kernel_launch(void* const* d_in, const int* in_sizes, int n_in,
                              void* d_out, int out_size) {
    const float* X  = (const float*)d_in[0];   // node_feats [S, G*B, C]
    const float* W  = (const float*)d_in[1];   // weight [P, C]
    const float* sf = (const float*)d_in[2];   // smooth_factor [P]
    float* out = (float*)d_out;                // [outputs (G,P,C) | assign (N,P)]
    float* assign_out = out + OUT_ELEMS;

    prep_kernel<<<1, 64>>>(W, sf);
    assign_tc<<<N / BM, 128>>>(X, assign_out);
    gemm2_mma<<<dim3(C / 64, G, KS), 128>>>(X);
    reduce_kernel<<<(OUT_ELEMS / 4 + 255) / 256, 256>>>(out);
}

// round 9
// speedup vs baseline: 2.8170x; 1.0046x over previous
#include <cuda_runtime.h>
#include <cuda_bf16.h>
#include <cstdint>

// ---------- problem constants (fixed instance) ----------
constexpr int S = 3, G = 8, B = 2048, C = 512, P = 64;
constexpr int N = S * G * B;              // 49152
constexpr int OUT_ELEMS = G * P * C;      // 262144
constexpr int KS = 8;                     // split-K for GEMM2
constexpr int KCHUNK = 768;               // 8*768 == 6144 exactly
constexpr int NS2 = KCHUNK / 16;          // 48 stages of k=16

// ---------- device scratch (no allocations allowed) ----------
__device__ float g_csq[P];
__device__ float g_ivb[P];
__device__ float g_partial[(size_t)KS * OUT_ELEMS];
__device__ __nv_bfloat16 g_whi[P * C];
__device__ __nv_bfloat16 g_wlo[P * C];
__device__ __nv_bfloat16 g_ahi[(size_t)N * P];
__device__ __nv_bfloat16 g_alo[(size_t)N * P];

// ---------- small helpers ----------
__device__ __forceinline__ uint32_t smem_u32(const void* p) {
    uint32_t a;
    asm("{ .reg .u64 t; cvta.to.shared.u64 t, %1; cvt.u32.u64 %0, t; }" : "=r"(a) : "l"(p));
    return a;
}
__device__ __forceinline__ void bfsplit2(float f0, float f1, uint32_t& ph, uint32_t& pl) {
    asm("cvt.rn.bf16x2.f32 %0, %1, %2;" : "=r"(ph) : "f"(f1), "f"(f0));
    float h0 = __uint_as_float(ph << 16);
    float h1 = __uint_as_float(ph & 0xFFFF0000u);
    float l0 = f0 - h0, l1 = f1 - h1;
    asm("cvt.rn.bf16x2.f32 %0, %1, %2;" : "=r"(pl) : "f"(l1), "f"(l0));
}
__device__ __forceinline__ void mma16816(float* d, const uint32_t* a, const uint32_t* b) {
    asm volatile(
        "mma.sync.aligned.m16n8k16.row.col.f32.bf16.bf16.f32 "
        "{%0,%1,%2,%3}, {%4,%5,%6,%7}, {%8,%9}, {%0,%1,%2,%3};"
        : "+f"(d[0]), "+f"(d[1]), "+f"(d[2]), "+f"(d[3])
        : "r"(a[0]), "r"(a[1]), "r"(a[2]), "r"(a[3]), "r"(b[0]), "r"(b[1]));
}
__device__ __forceinline__ void ldmx2t(uint32_t& r0, uint32_t& r1, uint32_t addr) {
    asm volatile("ldmatrix.sync.aligned.m8n8.x2.trans.shared.b16 {%0,%1}, [%2];"
                 : "=r"(r0), "=r"(r1) : "r"(addr));
}
__device__ __forceinline__ void ldmx4(uint32_t* r, uint32_t addr) {
    asm volatile("ldmatrix.sync.aligned.m8n8.x4.shared.b16 {%0,%1,%2,%3}, [%4];"
                 : "=r"(r[0]), "=r"(r[1]), "=r"(r[2]), "=r"(r[3]) : "r"(addr));
}
__device__ __forceinline__ void ldmx4t(uint32_t* r, uint32_t addr) {
    asm volatile("ldmatrix.sync.aligned.m8n8.x4.trans.shared.b16 {%0,%1,%2,%3}, [%4];"
                 : "=r"(r[0]), "=r"(r[1]), "=r"(r[2]), "=r"(r[3]) : "r"(addr));
}

// ---------- prep: |c|^2, 1/beta, W split to bf16 hi/lo ----------
__global__ void prep_kernel(const float* __restrict__ W, const float* __restrict__ sf) {
    int p = threadIdx.x;
    if (p >= P) return;
    const float* wr = W + (size_t)p * C;
    float s = 0.f;
    uint32_t* whi = reinterpret_cast<uint32_t*>(g_whi + (size_t)p * C);
    uint32_t* wlo = reinterpret_cast<uint32_t*>(g_wlo + (size_t)p * C);
#pragma unroll 4
    for (int k = 0; k < C; k += 2) {
        float f0 = wr[k], f1 = wr[k + 1];
        s += f0 * f0 + f1 * f1;
        uint32_t h, l;
        bfsplit2(f0, f1, h, l);
        whi[k >> 1] = h;
        wlo[k >> 1] = l;
    }
    g_csq[p] = s;
    g_ivb[p] = 1.0f + __expf(-sf[p]);   // 1/sigmoid(sf)
}

// ---------- fused GEMM1 (HMMA split x3) + softmax -> assign ----------
constexpr int BM = 128;
constexpr int APAD = 24;   // halves per smem row (48 B)

__global__ __launch_bounds__(128) void assign_tc(
    const float* __restrict__ X, float* __restrict__ assign_out)
{
    __shared__ __align__(16) __nv_bfloat16 AsH[2][BM][APAD];
    __shared__ __align__(16) __nv_bfloat16 AsL[2][BM][APAD];
    __shared__ __align__(16) __nv_bfloat16 WsH[2][P][APAD];
    __shared__ __align__(16) __nv_bfloat16 WsL[2][P][APAD];
    __shared__ float Xsq[BM];
    __shared__ float Csq[P];
    __shared__ float Ivb[P];

    const int t = threadIdx.x;
    const int w = t >> 5;
    const int lane = t & 31;
    const int g8 = lane >> 2;
    const int t4 = lane & 3;
    const int row_base = blockIdx.x * BM;

    if (t < P) { Csq[t] = g_csq[t]; Ivb[t] = g_ivb[t]; }

    // ---- coalesced loader roles ----
    // X: 4 lanes per row; thread covers rows xr, xr+32, xr+64, xr+96, k-quad xq
    const int xr = t >> 2;
    const int xq = t & 3;
    // W: 2 lanes per row from pre-split bf16; rows wr0, wr0+32; chunk wc
    const bool wlo_role = t >= 64;
    const int u = t & 63;
    const int wr0 = u >> 1;
    const int wc = u & 1;
    const __nv_bfloat16* wsrc = wlo_role ? g_wlo : g_whi;

    const uint32_t aHb = smem_u32(AsH), aLb = smem_u32(AsL);
    const uint32_t wHb = smem_u32(WsH), wLb = smem_u32(WsL);
    const uint32_t aoff = (uint32_t)(w * 32 + (lane & 7) + ((lane >> 3) & 1) * 8) * 48
                        + ((lane >> 4) & 1) * 16;
    const uint32_t boff = (uint32_t)((lane & 7) + ((lane >> 4) & 1) * 8) * 48
                        + ((lane >> 3) & 1) * 16;

    float acc[2][8][4];
#pragma unroll
    for (int mi = 0; mi < 2; mi++)
#pragma unroll
        for (int ni = 0; ni < 8; ni++)
#pragma unroll
            for (int q = 0; q < 4; q++) acc[mi][ni][q] = 0.f;

    float xp[4] = {0.f, 0.f, 0.f, 0.f};
    float4 xv[4];
    uint4 wv0, wv1;

    auto gl_load = [&](int s) {
        const int k0 = s * 16;
#pragma unroll
        for (int i = 0; i < 4; i++)
            xv[i] = *reinterpret_cast<const float4*>(
                X + (size_t)(row_base + xr + 32 * i) * C + k0 + xq * 4);
        wv0 = *reinterpret_cast<const uint4*>(wsrc + (size_t)wr0 * C + k0 + wc * 8);
        wv1 = *reinterpret_cast<const uint4*>(wsrc + (size_t)(wr0 + 32) * C + k0 + wc * 8);
    };
    auto st_stage = [&](int b) {
#pragma unroll
        for (int i = 0; i < 4; i++) {
            uint32_t h0, l0, h1, l1;
            bfsplit2(xv[i].x, xv[i].y, h0, l0);
            bfsplit2(xv[i].z, xv[i].w, h1, l1);
            xp[i] += xv[i].x * xv[i].x + xv[i].y * xv[i].y +
                     xv[i].z * xv[i].z + xv[i].w * xv[i].w;
            *reinterpret_cast<uint2*>(&AsH[b][xr + 32 * i][xq * 4]) = make_uint2(h0, h1);
            *reinterpret_cast<uint2*>(&AsL[b][xr + 32 * i][xq * 4]) = make_uint2(l0, l1);
        }
        if (!wlo_role) {
            *reinterpret_cast<uint4*>(&WsH[b][wr0][wc * 8]) = wv0;
            *reinterpret_cast<uint4*>(&WsH[b][wr0 + 32][wc * 8]) = wv1;
        } else {
            *reinterpret_cast<uint4*>(&WsL[b][wr0][wc * 8]) = wv0;
            *reinterpret_cast<uint4*>(&WsL[b][wr0 + 32][wc * 8]) = wv1;
        }
    };

    gl_load(0);
    st_stage(0);
    __syncthreads();

#pragma unroll 1
    for (int s = 0; s < 32; s++) {
        const int b = s & 1;
        if (s + 1 < 32) gl_load(s + 1);

        uint32_t bh[8][2], bl[8][2];
#pragma unroll
        for (int np = 0; np < 4; np++) {
            uint32_t r[4];
            ldmx4(r, wHb + (uint32_t)b * 3072 + boff + np * 768);
            bh[2 * np][0] = r[0]; bh[2 * np][1] = r[1];
            bh[2 * np + 1][0] = r[2]; bh[2 * np + 1][1] = r[3];
            ldmx4(r, wLb + (uint32_t)b * 3072 + boff + np * 768);
            bl[2 * np][0] = r[0]; bl[2 * np][1] = r[1];
            bl[2 * np + 1][0] = r[2]; bl[2 * np + 1][1] = r[3];
        }
#pragma unroll
        for (int mi = 0; mi < 2; mi++) {
            uint32_t ah[4], al_[4];
            ldmx4(ah, aHb + (uint32_t)b * 6144 + aoff + mi * 768);
            ldmx4(al_, aLb + (uint32_t)b * 6144 + aoff + mi * 768);
#pragma unroll
            for (int ni = 0; ni < 8; ni++) {
                mma16816(acc[mi][ni], ah, bh[ni]);
                mma16816(acc[mi][ni], ah, bl[ni]);
                mma16816(acc[mi][ni], al_, bh[ni]);
            }
        }

        if (s + 1 < 32) st_stage(b ^ 1);
        __syncthreads();
    }

    // |x|^2: reduce over the 4-lane quad owning each row
#pragma unroll
    for (int i = 0; i < 4; i++) {
        float sx = xp[i];
        sx += __shfl_xor_sync(0xffffffffu, sx, 1);
        sx += __shfl_xor_sync(0xffffffffu, sx, 2);
        if (xq == 0) Xsq[xr + 32 * i] = sx;
    }
    __syncthreads();

    // ---- softmax epilogue from accumulators ----
    float csq_c[16], ivb_c[16];
#pragma unroll
    for (int ni = 0; ni < 8; ni++)
#pragma unroll
        for (int j = 0; j < 2; j++) {
            const int c = ni * 8 + t4 * 2 + j;
            csq_c[2 * ni + j] = Csq[c];
            ivb_c[2 * ni + j] = Ivb[c];
        }

#pragma unroll
    for (int mi = 0; mi < 2; mi++) {
#pragma unroll
        for (int half = 0; half < 2; half++) {
            const int rl = w * 32 + mi * 16 + half * 8 + g8;
            const float xs = Xsq[rl];
            float v[16];
#pragma unroll
            for (int ni = 0; ni < 8; ni++)
#pragma unroll
                for (int j = 0; j < 2; j++)
                    v[2 * ni + j] = fminf(2.f * acc[mi][ni][2 * half + j] - xs - csq_c[2 * ni + j], 0.f)
                                    * ivb_c[2 * ni + j];
            float m = v[0];
#pragma unroll
            for (int q = 1; q < 16; q++) m = fmaxf(m, v[q]);
            m = fmaxf(m, __shfl_xor_sync(0xffffffffu, m, 1));
            m = fmaxf(m, __shfl_xor_sync(0xffffffffu, m, 2));
            float sum = 0.f;
#pragma unroll
            for (int q = 0; q < 16; q++) { float ex = __expf(v[q] - m); v[q] = ex; sum += ex; }
            sum += __shfl_xor_sync(0xffffffffu, sum, 1);
            sum += __shfl_xor_sync(0xffffffffu, sum, 2);
            const float inv = 1.f / sum;
            const size_t arow = (size_t)(row_base + rl);
            float* orow = assign_out + arow * P + t4 * 2;
            uint32_t* ahp = reinterpret_cast<uint32_t*>(g_ahi) + arow * 32 + t4;
            uint32_t* alp = reinterpret_cast<uint32_t*>(g_alo) + arow * 32 + t4;
#pragma unroll
            for (int ni = 0; ni < 8; ni++) {
                const float a0 = v[2 * ni] * inv, a1 = v[2 * ni + 1] * inv;
                *reinterpret_cast<float2*>(orow + ni * 8) = make_float2(a0, a1);
                uint32_t hh, ll;
                bfsplit2(a0, a1, hh, ll);
                ahp[ni * 4] = hh;
                alp[ni * 4] = ll;
            }
        }
    }
}

// ---------- GEMM2 on HMMA: pre-split assign (bf16), ldmatrix A-frags ----------
constexpr int STR2 = 72;   // halves per smem row (144 B) — conflict-free ldmatrix

__global__ __launch_bounds__(128) void gemm2_mma(const float* __restrict__ X)
{
    __shared__ __align__(16) __nv_bfloat16 AsH[2][16][STR2];
    __shared__ __align__(16) __nv_bfloat16 AsL[2][16][STR2];
    __shared__ __align__(16) __nv_bfloat16 BsH[2][16][STR2];
    __shared__ __align__(16) __nv_bfloat16 BsL[2][16][STR2];

    const int t = threadIdx.x;
    const int w = t >> 5;
    const int lane = t & 31;
    const int g8 = lane >> 2;
    const int tid4 = lane & 3;

    const int ct = blockIdx.x;
    const int gg = blockIdx.y;
    const int ks = blockIdx.z;
    const int cbase = ct * 64;
    const int jbase0 = ks * KCHUNK;

    // loader: krow = k-row in stage, chunk = 8-half chunk
    const int krow = t >> 3;
    const int chunk = t & 7;

    const uint32_t aH = smem_u32(AsH), aL = smem_u32(AsL);
    const uint32_t bH = smem_u32(BsH), bL = smem_u32(BsL);
    // ldmatrix.x4.trans A-frag lane offset (bytes), + p0*2 per mi
    const uint32_t aoffT = (uint32_t)((lane & 7) + ((lane >> 4) & 1) * 8) * (STR2 * 2)
                         + ((lane >> 3) & 1) * 16;
    const int lrow = lane & 15;

    float acc[4][2][4];
#pragma unroll
    for (int mi = 0; mi < 4; mi++)
#pragma unroll
        for (int ni = 0; ni < 2; ni++)
#pragma unroll
            for (int q = 0; q < 4; q++) acc[mi][ni][q] = 0.f;

    uint4 av0, av1;
    float4 xv0, xv1;

    auto gl_load = [&](int s) {
        const int j = jbase0 + s * 16 + krow;
        const size_t row = (size_t)(j >> 11) * (G * B) + (size_t)gg * B + (j & 2047);
        av0 = *reinterpret_cast<const uint4*>(g_ahi + row * P + chunk * 8);
        av1 = *reinterpret_cast<const uint4*>(g_alo + row * P + chunk * 8);
        const float* xp = X + row * C + cbase + chunk * 8;
        xv0 = *reinterpret_cast<const float4*>(xp);
        xv1 = *reinterpret_cast<const float4*>(xp + 4);
    };
    auto st_stage = [&](int b) {
        *reinterpret_cast<uint4*>(&AsH[b][krow][chunk * 8]) = av0;
        *reinterpret_cast<uint4*>(&AsL[b][krow][chunk * 8]) = av1;
        uint32_t h[4], l[4];
        bfsplit2(xv0.x, xv0.y, h[0], l[0]);
        bfsplit2(xv0.z, xv0.w, h[1], l[1]);
        bfsplit2(xv1.x, xv1.y, h[2], l[2]);
        bfsplit2(xv1.z, xv1.w, h[3], l[3]);
        *reinterpret_cast<uint4*>(&BsH[b][krow][chunk * 8]) = make_uint4(h[0], h[1], h[2], h[3]);
        *reinterpret_cast<uint4*>(&BsL[b][krow][chunk * 8]) = make_uint4(l[0], l[1], l[2], l[3]);
    };

    gl_load(0);
    st_stage(0);
    __syncthreads();

#pragma unroll 1
    for (int s = 0; s < NS2; s++) {
        const int b = s & 1;
        if (s + 1 < NS2) gl_load(s + 1);

        // B fragments (c strip for this warp)
        uint32_t bh[2][2], bl[2][2];
#pragma unroll
        for (int ni = 0; ni < 2; ni++) {
            const uint32_t off =
                (uint32_t)((b * 16 + lrow) * STR2 + (w * 16 + ni * 8)) * 2;
            ldmx2t(bh[ni][0], bh[ni][1], bH + off);
            ldmx2t(bl[ni][0], bl[ni][1], bL + off);
        }
#pragma unroll
        for (int mi = 0; mi < 4; mi++) {
            uint32_t ah[4], al_[4];
            const uint32_t ao = (uint32_t)b * (16 * STR2 * 2) + aoffT + mi * 32;
            ldmx4t(ah, aH + ao);
            ldmx4t(al_, aL + ao);
#pragma unroll
            for (int ni = 0; ni < 2; ni++) {
                mma16816(acc[mi][ni], ah, bh[ni]);
                mma16816(acc[mi][ni], ah, bl[ni]);
                mma16816(acc[mi][ni], al_, bh[ni]);
            }
        }

        if (s + 1 < NS2) st_stage(b ^ 1);
        __syncthreads();
    }

    float* dst = g_partial + ((size_t)ks * G + gg) * (size_t)(P * C);
#pragma unroll
    for (int mi = 0; mi < 4; mi++) {
        const int p0_ = mi * 16 + g8;
#pragma unroll
        for (int ni = 0; ni < 2; ni++) {
            const int cc = cbase + w * 16 + ni * 8 + tid4 * 2;
            *reinterpret_cast<float2*>(dst + (size_t)p0_ * C + cc) =
                make_float2(acc[mi][ni][0], acc[mi][ni][1]);
            *reinterpret_cast<float2*>(dst + (size_t)(p0_ + 8) * C + cc) =
                make_float2(acc[mi][ni][2], acc[mi][ni][3]);
        }
    }
}

// ---------- deterministic split-K reduction (vectorized) ----------
__global__ void reduce_kernel(float* __restrict__ out) {
    const int i = blockIdx.x * blockDim.x + threadIdx.x;
    if (i < OUT_ELEMS / 4) {
        const float4* src = reinterpret_cast<const float4*>(g_partial);
        float4 s = src[i];
#pragma unroll
        for (int ks = 1; ks < KS; ks++) {
            float4 v = src[(size_t)ks * (OUT_ELEMS / 4) + i];
            s.x += v.x; s.y += v.y; s.z += v.z; s.w += v.w;
        }
        reinterpret_cast<float4*>(out)[i] = s;
    }
}

// ---------- launch ----------
extern "C" void kernel_launch(void* const* d_in, const int* in_sizes, int n_in,
                              void* d_out, int out_size) {
    const float* X  = (const float*)d_in[0];   // node_feats [S, G*B, C]
    const float* W  = (const float*)d_in[1];   // weight [P, C]
    const float* sf = (const float*)d_in[2];   // smooth_factor [P]
    float* out = (float*)d_out;                // [outputs (G,P,C) | assign (N,P)]
    float* assign_out = out + OUT_ELEMS;

    prep_kernel<<<1, 64>>>(W, sf);
    assign_tc<<<N / BM, 128>>>(X, assign_out);
    gemm2_mma<<<dim3(C / 64, G, KS), 128>>>(X);
    reduce_kernel<<<(OUT_ELEMS / 4 + 255) / 256, 256>>>(out);
}